// round 10
// baseline (speedup 1.0000x reference)
#include <cuda_runtime.h>
#include <math.h>

// ---------------- problem dims ----------------
#define Bsz 4
#define Nq  1024
#define Mctx 512
#define Dm  512
#define Pm  256
#define Hh  8
#define DHh 64
#define Ll  6
#define FIi 2048
#define LDS_ 1040

// ---------------- device scratch ----------------
__device__ float g_X   [(long)Bsz*Nq*Dm];
__device__ float g_XN  [(long)Bsz*Nq*Dm];
__device__ float g_Q   [(long)Bsz*Nq*Dm];
__device__ float g_QKV [(long)Bsz*Nq*640];
__device__ float g_O   [(long)Bsz*Nq*Dm];
__device__ float g_T   [(long)Bsz*Nq*Dm];
__device__ float g_KVp [(long)Bsz*Nq*128];
__device__ float g_Kt  [(long)Bsz*64*LDS_];
__device__ float g_V   [(long)Bsz*LDS_*64];
__device__ float g_H1  [(long)Bsz*Nq*2*FIi];
__device__ float g_CTXN[(long)Bsz*Mctx*Pm];
__device__ float g_Wqkv[(long)Ll*Dm*640];

// ---------------- helpers ----------------
__device__ __forceinline__ float f2tf(float f) {
    unsigned u;
    asm("cvt.rna.tf32.f32 %0, %1;" : "=r"(u) : "f"(f));
    return __uint_as_float(u);
}

__device__ __forceinline__ void mma_tf32(float* d, const unsigned* a, const unsigned* b) {
    asm volatile(
        "mma.sync.aligned.m16n8k8.row.col.f32.tf32.tf32.f32 "
        "{%0,%1,%2,%3}, {%4,%5,%6,%7}, {%8,%9}, {%0,%1,%2,%3};"
        : "+f"(d[0]), "+f"(d[1]), "+f"(d[2]), "+f"(d[3])
        : "r"(a[0]), "r"(a[1]), "r"(a[2]), "r"(a[3]), "r"(b[0]), "r"(b[1]));
}

__device__ __forceinline__ float siluf(float g) {
    return g / (1.0f + expf(-g));
}

__device__ __forceinline__ float blockMax(float v, float* sred) {
    #pragma unroll
    for (int o = 16; o; o >>= 1) v = fmaxf(v, __shfl_xor_sync(0xffffffffu, v, o));
    int tid = threadIdx.x;
    if ((tid & 31) == 0) sred[tid >> 5] = v;
    __syncthreads();
    if (tid < 32) {
        float t = (tid < 8) ? sred[tid] : -3.4e38f;
        #pragma unroll
        for (int o = 4; o; o >>= 1) t = fmaxf(t, __shfl_xor_sync(0xffffffffu, t, o));
        if (tid == 0) sred[0] = t;
    }
    __syncthreads();
    float r = sred[0];
    __syncthreads();
    return r;
}

__device__ __forceinline__ float blockSum(float v, float* sred) {
    #pragma unroll
    for (int o = 16; o; o >>= 1) v += __shfl_xor_sync(0xffffffffu, v, o);
    int tid = threadIdx.x;
    if ((tid & 31) == 0) sred[tid >> 5] = v;
    __syncthreads();
    if (tid < 32) {
        float t = (tid < 8) ? sred[tid] : 0.f;
        #pragma unroll
        for (int o = 4; o; o >>= 1) t += __shfl_xor_sync(0xffffffffu, t, o);
        if (tid == 0) sred[0] = t;
    }
    __syncthreads();
    float r = sred[0];
    __syncthreads();
    return r;
}

// ---------------- weight pack: W[l][k][0..639] = [wq | wkv] ----------------
__global__ __launch_bounds__(256) void pack_qkv(
    const float* __restrict__ wq, const float* __restrict__ wkv,
    float* __restrict__ W)
{
    long i4 = (long)blockIdx.x * 256 + threadIdx.x;
    long c4 = i4 % 160, rk = i4 / 160;
    float4 v;
    if (c4 < 128) v = *(const float4*)(wq + rk * 512 + c4 * 4);
    else          v = *(const float4*)(wkv + rk * 128 + (c4 - 128) * 4);
    *(float4*)(W + rk * 640 + c4 * 4) = v;
}

// ---------------- tf32 tensor-core GEMM: C = A @ B (+Res), A optionally gated --
// GATE: A'[m][k] = A[m][k] * silu(A[m][k+2048])  (ff2 path, lda=4096, K=2048)
template<int FUSE, int GATE>
__global__ __launch_bounds__(256, 2) void tgemm_k(
    const float* __restrict__ A, int lda, long sAb, long sAh,
    const float* __restrict__ Bm, int ldb, long sBb, long sBh,
    float* __restrict__ C, int ldc, long sCb, long sCh,
    const float* __restrict__ Res, int ldr,
    int N, int K, int HH)
{
    int z = blockIdx.z;
    int zb = z / HH, zh = z - zb * HH;
    A  += zb * sAb + zh * sAh;
    Bm += zb * sBb + zh * sBh;
    C  += zb * sCb + zh * sCh;

    __shared__ float As[2][128][20];
    __shared__ float Bs[2][16][136];

    const int tid  = threadIdx.x;
    const int lane = tid & 31;
    const int warp = tid >> 5;
    const int wm = warp >> 2;
    const int wn = warp & 3;
    const int row0 = blockIdx.y << 7;
    const int col0 = blockIdx.x << 7;

    const int am = tid >> 2;
    const int ak = (tid & 3) << 2;
    const int bk = tid >> 5;
    const int bn = (tid & 31) << 2;

    float acc[4][4][4];
    #pragma unroll
    for (int mi = 0; mi < 4; mi++)
        #pragma unroll
        for (int ni = 0; ni < 4; ni++)
            #pragma unroll
            for (int c = 0; c < 4; c++) acc[mi][ni][c] = 0.f;

    {
        #pragma unroll
        for (int it = 0; it < 2; it++) {
            int m = am + it * 64;
            float4 av = *(const float4*)(A + (long)(row0 + m) * lda + ak);
            if (GATE) {
                float4 gv = *(const float4*)(A + (long)(row0 + m) * lda + ak + 2048);
                av.x *= siluf(gv.x); av.y *= siluf(gv.y);
                av.z *= siluf(gv.z); av.w *= siluf(gv.w);
            }
            As[0][m][ak + 0] = f2tf(av.x);
            As[0][m][ak + 1] = f2tf(av.y);
            As[0][m][ak + 2] = f2tf(av.z);
            As[0][m][ak + 3] = f2tf(av.w);
        }
        #pragma unroll
        for (int it = 0; it < 2; it++) {
            int k = bk + it * 8;
            int col = col0 + bn;
            float4 bv = make_float4(0.f, 0.f, 0.f, 0.f);
            if (col < N) bv = *(const float4*)(Bm + (long)k * ldb + col);
            Bs[0][k][bn + 0] = f2tf(bv.x);
            Bs[0][k][bn + 1] = f2tf(bv.y);
            Bs[0][k][bn + 2] = f2tf(bv.z);
            Bs[0][k][bn + 3] = f2tf(bv.w);
        }
    }
    __syncthreads();

    const int gr = lane >> 2;
    const int gk = lane & 3;

    int buf = 0;
    for (int k0 = 0; k0 < K; k0 += 16) {
        bool hasNext = (k0 + 16 < K);
        float4 pa0, pa1, pg0, pg1, pb0, pb1;
        if (hasNext) {
            pa0 = *(const float4*)(A + (long)(row0 + am)      * lda + k0 + 16 + ak);
            pa1 = *(const float4*)(A + (long)(row0 + am + 64) * lda + k0 + 16 + ak);
            if (GATE) {
                pg0 = *(const float4*)(A + (long)(row0 + am)      * lda + k0 + 16 + ak + 2048);
                pg1 = *(const float4*)(A + (long)(row0 + am + 64) * lda + k0 + 16 + ak + 2048);
            }
            int col = col0 + bn;
            pb0 = make_float4(0.f, 0.f, 0.f, 0.f);
            pb1 = pb0;
            if (col < N) {
                pb0 = *(const float4*)(Bm + (long)(k0 + 16 + bk)     * ldb + col);
                pb1 = *(const float4*)(Bm + (long)(k0 + 16 + bk + 8) * ldb + col);
            }
        }

        #pragma unroll
        for (int ks = 0; ks < 16; ks += 8) {
            unsigned a[4][4], b[4][2];
            #pragma unroll
            for (int mi = 0; mi < 4; mi++) {
                int r = wm * 64 + mi * 16 + gr;
                a[mi][0] = __float_as_uint(As[buf][r    ][ks + gk]);
                a[mi][1] = __float_as_uint(As[buf][r + 8][ks + gk]);
                a[mi][2] = __float_as_uint(As[buf][r    ][ks + gk + 4]);
                a[mi][3] = __float_as_uint(As[buf][r + 8][ks + gk + 4]);
            }
            #pragma unroll
            for (int ni = 0; ni < 4; ni++) {
                int c = wn * 32 + ni * 8 + gr;
                b[ni][0] = __float_as_uint(Bs[buf][ks + gk    ][c]);
                b[ni][1] = __float_as_uint(Bs[buf][ks + gk + 4][c]);
            }
            #pragma unroll
            for (int mi = 0; mi < 4; mi++)
                #pragma unroll
                for (int ni = 0; ni < 4; ni++)
                    mma_tf32(acc[mi][ni], a[mi], b[ni]);
        }

        if (hasNext) {
            if (GATE) {
                pa0.x *= siluf(pg0.x); pa0.y *= siluf(pg0.y);
                pa0.z *= siluf(pg0.z); pa0.w *= siluf(pg0.w);
                pa1.x *= siluf(pg1.x); pa1.y *= siluf(pg1.y);
                pa1.z *= siluf(pg1.z); pa1.w *= siluf(pg1.w);
            }
            As[buf ^ 1][am][ak + 0] = f2tf(pa0.x);
            As[buf ^ 1][am][ak + 1] = f2tf(pa0.y);
            As[buf ^ 1][am][ak + 2] = f2tf(pa0.z);
            As[buf ^ 1][am][ak + 3] = f2tf(pa0.w);
            As[buf ^ 1][am + 64][ak + 0] = f2tf(pa1.x);
            As[buf ^ 1][am + 64][ak + 1] = f2tf(pa1.y);
            As[buf ^ 1][am + 64][ak + 2] = f2tf(pa1.z);
            As[buf ^ 1][am + 64][ak + 3] = f2tf(pa1.w);
            Bs[buf ^ 1][bk][bn + 0] = f2tf(pb0.x);
            Bs[buf ^ 1][bk][bn + 1] = f2tf(pb0.y);
            Bs[buf ^ 1][bk][bn + 2] = f2tf(pb0.z);
            Bs[buf ^ 1][bk][bn + 3] = f2tf(pb0.w);
            Bs[buf ^ 1][bk + 8][bn + 0] = f2tf(pb1.x);
            Bs[buf ^ 1][bk + 8][bn + 1] = f2tf(pb1.y);
            Bs[buf ^ 1][bk + 8][bn + 2] = f2tf(pb1.z);
            Bs[buf ^ 1][bk + 8][bn + 3] = f2tf(pb1.w);
        }
        __syncthreads();
        buf ^= 1;
    }

    bool fullN = (col0 + 128 <= N);
    #pragma unroll
    for (int mi = 0; mi < 4; mi++) {
        #pragma unroll
        for (int ni = 0; ni < 4; ni++) {
            int r  = row0 + wm * 64 + mi * 16 + gr;
            int cc = col0 + wn * 32 + ni * 8 + gk * 2;
            float* c0p = C + (long)r * ldc + cc;
            float* c2p = C + (long)(r + 8) * ldc + cc;
            float v0 = acc[mi][ni][0], v1 = acc[mi][ni][1];
            float v2 = acc[mi][ni][2], v3 = acc[mi][ni][3];
            if (FUSE) {
                const float* r0p = Res + (long)r * ldr + cc;
                const float* r2p = Res + (long)(r + 8) * ldr + cc;
                if (fullN) {
                    float2 q0 = *(const float2*)r0p;
                    float2 q2 = *(const float2*)r2p;
                    v0 += q0.x; v1 += q0.y; v2 += q2.x; v3 += q2.y;
                } else {
                    if (cc     < N) { v0 += r0p[0]; v2 += r2p[0]; }
                    if (cc + 1 < N) { v1 += r0p[1]; v3 += r2p[1]; }
                }
            }
            if (fullN) {
                *(float2*)c0p = make_float2(v0, v1);
                *(float2*)c2p = make_float2(v2, v3);
            } else {
                if (cc     < N) { c0p[0] = v0; c2p[0] = v2; }
                if (cc + 1 < N) { c0p[1] = v1; c2p[1] = v3; }
            }
        }
    }
}

// ---------------- small 64x64-tile tf32 GEMM ----------------
__global__ __launch_bounds__(128) void sgemm64_k(
    const float* __restrict__ A, int lda,
    const float* __restrict__ Bm, int ldb,
    float* __restrict__ C, int ldc, int K)
{
    __shared__ float As[64][20];
    __shared__ float Bs[16][72];
    const int tid = threadIdx.x;
    const int lane = tid & 31, warp = tid >> 5;
    const int wm = warp >> 1, wn = warp & 1;
    const int row0 = blockIdx.y << 6, col0 = blockIdx.x << 6;
    const int gr = lane >> 2, gk = lane & 3;

    const int am = tid >> 1, ak = (tid & 1) * 8;
    const int bkr = tid >> 3, bc = (tid & 7) * 8;

    float acc[2][4][4];
    #pragma unroll
    for (int mi = 0; mi < 2; mi++)
        #pragma unroll
        for (int ni = 0; ni < 4; ni++)
            #pragma unroll
            for (int e = 0; e < 4; e++) acc[mi][ni][e] = 0.f;

    for (int k0 = 0; k0 < K; k0 += 16) {
        float4 a0 = *(const float4*)(A + (long)(row0 + am) * lda + k0 + ak);
        float4 a1 = *(const float4*)(A + (long)(row0 + am) * lda + k0 + ak + 4);
        As[am][ak + 0] = f2tf(a0.x); As[am][ak + 1] = f2tf(a0.y);
        As[am][ak + 2] = f2tf(a0.z); As[am][ak + 3] = f2tf(a0.w);
        As[am][ak + 4] = f2tf(a1.x); As[am][ak + 5] = f2tf(a1.y);
        As[am][ak + 6] = f2tf(a1.z); As[am][ak + 7] = f2tf(a1.w);
        float4 b0 = *(const float4*)(Bm + (long)(k0 + bkr) * ldb + col0 + bc);
        float4 b1 = *(const float4*)(Bm + (long)(k0 + bkr) * ldb + col0 + bc + 4);
        Bs[bkr][bc + 0] = f2tf(b0.x); Bs[bkr][bc + 1] = f2tf(b0.y);
        Bs[bkr][bc + 2] = f2tf(b0.z); Bs[bkr][bc + 3] = f2tf(b0.w);
        Bs[bkr][bc + 4] = f2tf(b1.x); Bs[bkr][bc + 5] = f2tf(b1.y);
        Bs[bkr][bc + 6] = f2tf(b1.z); Bs[bkr][bc + 7] = f2tf(b1.w);
        __syncthreads();
        #pragma unroll
        for (int ks = 0; ks < 16; ks += 8) {
            unsigned a[2][4], b[4][2];
            #pragma unroll
            for (int mi = 0; mi < 2; mi++) {
                int r = wm * 32 + mi * 16 + gr;
                a[mi][0] = __float_as_uint(As[r    ][ks + gk]);
                a[mi][1] = __float_as_uint(As[r + 8][ks + gk]);
                a[mi][2] = __float_as_uint(As[r    ][ks + gk + 4]);
                a[mi][3] = __float_as_uint(As[r + 8][ks + gk + 4]);
            }
            #pragma unroll
            for (int ni = 0; ni < 4; ni++) {
                int c = wn * 32 + ni * 8 + gr;
                b[ni][0] = __float_as_uint(Bs[ks + gk    ][c]);
                b[ni][1] = __float_as_uint(Bs[ks + gk + 4][c]);
            }
            #pragma unroll
            for (int mi = 0; mi < 2; mi++)
                #pragma unroll
                for (int ni = 0; ni < 4; ni++)
                    mma_tf32(acc[mi][ni], a[mi], b[ni]);
        }
        __syncthreads();
    }

    #pragma unroll
    for (int mi = 0; mi < 2; mi++)
        #pragma unroll
        for (int ni = 0; ni < 4; ni++) {
            int r  = row0 + wm * 32 + mi * 16 + gr;
            int cc = col0 + wn * 32 + ni * 8 + gk * 2;
            *(float2*)(C + (long)r * ldc + cc)       = make_float2(acc[mi][ni][0], acc[mi][ni][1]);
            *(float2*)(C + (long)(r + 8) * ldc + cc) = make_float2(acc[mi][ni][2], acc[mi][ni][3]);
        }
}

// ---------------- fused flash attention ----------------
template<bool CAUSAL>
__global__ __launch_bounds__(128) void flash_attn(
    const float* __restrict__ Q, int ldq,
    const float* __restrict__ Kt,
    const float* __restrict__ V,
    float* __restrict__ O,
    const float* __restrict__ emb,
    int Ltot)
{
    extern __shared__ float sm[];
    float (*Qs)[68] = (float(*)[68])sm;
    float (*Ks)[68] = (float(*)[68])(sm + 64 * 68);
    float (*Vs)[68] = (float(*)[68])(sm + 2 * 64 * 68);
    float (*Ps)[68] = (float(*)[68])(sm + 3 * 64 * 68);
    float* biasLUT  = sm + 4 * 64 * 68;

    const int qi = blockIdx.x, h = blockIdx.y, b = blockIdx.z;
    const int q0 = qi << 6;
    const int tid = threadIdx.x;
    const int warp = tid >> 5, lane = tid & 31;
    const int gr = lane >> 2, gk = lane & 3;
    const int r0 = (warp << 4) + gr;

    if (CAUSAL) {
        for (int n = tid; n < 1024; n += 128) {
            int bucket;
            if (n < 16) bucket = n;
            else {
                int lg = (int)(logf((float)n * 0.0625f) * 7.69486038f);
                bucket = min(16 + lg, 31);
            }
            biasLUT[n] = emb[bucket * 8 + h];
        }
    }

    {
        const int row = tid >> 1, half = tid & 1;
        const float* srcp = Q + (long)(b * 1024 + q0 + row) * ldq + h * 64 + half * 32;
        float vals[32];
        #pragma unroll
        for (int e = 0; e < 8; e++)
            *(float4*)&vals[e * 4] = *(const float4*)(srcp + e * 4);
        if (CAUSAL && half == 0) {
            int t = q0 + row;
            #pragma unroll
            for (int i = 0; i < 16; i++) {
                float f = (float)t * powf(10000.0f, -(float)i * 0.0625f);
                float s, c; sincosf(f, &s, &c);
                float x1 = vals[i], x2 = vals[i + 16];
                vals[i]      = x1 * c - x2 * s;
                vals[i + 16] = x2 * c + x1 * s;
            }
        }
        #pragma unroll
        for (int i = 0; i < 32; i++)
            Qs[row][half * 32 + i] = f2tf(vals[i] * 0.125f);
    }

    float m0 = -1e30f, m1 = -1e30f, l0 = 0.f, l1 = 0.f;
    float co[8][4];
    #pragma unroll
    for (int nt = 0; nt < 8; nt++)
        #pragma unroll
        for (int e = 0; e < 4; e++) co[nt][e] = 0.f;

    const int ntiles = CAUSAL ? (qi + 2) : ((Ltot + 63) >> 6);

    for (int t = 0; t < ntiles; t++) {
        const int j0 = t << 6;
        __syncthreads();
        const float* ksrc = Kt + (long)b * 64 * LDS_ + j0;
        const float* vsrc = V + ((long)b * LDS_ + j0) * 64;
        if (j0 + 64 <= Ltot) {
            #pragma unroll
            for (int it = 0; it < 8; it++) {
                int idx = tid + it * 128;
                int r = idx >> 4, c4 = (idx & 15) << 2;
                float4 k4 = *(const float4*)(ksrc + (long)r * LDS_ + c4);
                Ks[r][c4 + 0] = f2tf(k4.x); Ks[r][c4 + 1] = f2tf(k4.y);
                Ks[r][c4 + 2] = f2tf(k4.z); Ks[r][c4 + 3] = f2tf(k4.w);
                float4 vv = *(const float4*)(vsrc + (long)r * 64 + c4);
                Vs[r][c4 + 0] = f2tf(vv.x); Vs[r][c4 + 1] = f2tf(vv.y);
                Vs[r][c4 + 2] = f2tf(vv.z); Vs[r][c4 + 3] = f2tf(vv.w);
            }
        } else {
            #pragma unroll
            for (int it = 0; it < 8; it++) {
                int idx = tid + it * 128;
                int r = idx >> 4, c4 = (idx & 15) << 2;
                #pragma unroll
                for (int e = 0; e < 4; e++) {
                    int jk = j0 + c4 + e;
                    Ks[r][c4 + e] = (jk < Ltot) ? f2tf(ksrc[(long)r * LDS_ + c4 + e]) : 0.f;
                }
                int jv = j0 + r;
                #pragma unroll
                for (int e = 0; e < 4; e++)
                    Vs[r][c4 + e] = (jv < Ltot) ? f2tf(vsrc[(long)r * 64 + c4 + e]) : 0.f;
            }
        }
        __syncthreads();

        float cs[8][4];
        #pragma unroll
        for (int nt = 0; nt < 8; nt++)
            #pragma unroll
            for (int e = 0; e < 4; e++) cs[nt][e] = 0.f;
        #pragma unroll
        for (int ks = 0; ks < 64; ks += 8) {
            unsigned a[4];
            a[0] = __float_as_uint(Qs[r0    ][ks + gk]);
            a[1] = __float_as_uint(Qs[r0 + 8][ks + gk]);
            a[2] = __float_as_uint(Qs[r0    ][ks + gk + 4]);
            a[3] = __float_as_uint(Qs[r0 + 8][ks + gk + 4]);
            #pragma unroll
            for (int nt = 0; nt < 8; nt++) {
                unsigned bb[2];
                bb[0] = __float_as_uint(Ks[ks + gk    ][nt * 8 + gr]);
                bb[1] = __float_as_uint(Ks[ks + gk + 4][nt * 8 + gr]);
                mma_tf32(cs[nt], a, bb);
            }
        }

        const int i0 = q0 + r0, i1 = i0 + 8;
        float tm0 = -1e30f, tm1 = -1e30f;
        #pragma unroll
        for (int nt = 0; nt < 8; nt++) {
            #pragma unroll
            for (int e = 0; e < 2; e++) {
                int jj = j0 + nt * 8 + gk * 2 + e;
                float s0 = cs[nt][e], s1 = cs[nt][2 + e];
                if (CAUSAL) {
                    s0 = (jj <= i0 + 1) ? s0 + biasLUT[max(i0 - jj, 0)] : -1e30f;
                    s1 = (jj <= i1 + 1) ? s1 + biasLUT[max(i1 - jj, 0)] : -1e30f;
                } else {
                    if (jj >= Ltot) { s0 = -1e30f; s1 = -1e30f; }
                }
                cs[nt][e] = s0; cs[nt][2 + e] = s1;
                tm0 = fmaxf(tm0, s0); tm1 = fmaxf(tm1, s1);
            }
        }
        tm0 = fmaxf(tm0, __shfl_xor_sync(0xffffffffu, tm0, 1));
        tm0 = fmaxf(tm0, __shfl_xor_sync(0xffffffffu, tm0, 2));
        tm1 = fmaxf(tm1, __shfl_xor_sync(0xffffffffu, tm1, 1));
        tm1 = fmaxf(tm1, __shfl_xor_sync(0xffffffffu, tm1, 2));

        float mn0 = fmaxf(m0, tm0), mn1 = fmaxf(m1, tm1);
        float sc0 = __expf(m0 - mn0), sc1 = __expf(m1 - mn1);
        float ps0 = 0.f, ps1 = 0.f;
        #pragma unroll
        for (int nt = 0; nt < 8; nt++) {
            float p00 = __expf(cs[nt][0] - mn0);
            float p01 = __expf(cs[nt][1] - mn0);
            float p10 = __expf(cs[nt][2] - mn1);
            float p11 = __expf(cs[nt][3] - mn1);
            ps0 += p00 + p01; ps1 += p10 + p11;
            int c = nt * 8 + gk * 2;
            *(float2*)&Ps[r0    ][c] = make_float2(f2tf(p00), f2tf(p01));
            *(float2*)&Ps[r0 + 8][c] = make_float2(f2tf(p10), f2tf(p11));
            co[nt][0] *= sc0; co[nt][1] *= sc0;
            co[nt][2] *= sc1; co[nt][3] *= sc1;
        }
        ps0 += __shfl_xor_sync(0xffffffffu, ps0, 1);
        ps0 += __shfl_xor_sync(0xffffffffu, ps0, 2);
        ps1 += __shfl_xor_sync(0xffffffffu, ps1, 1);
        ps1 += __shfl_xor_sync(0xffffffffu, ps1, 2);
        l0 = l0 * sc0 + ps0; l1 = l1 * sc1 + ps1;
        m0 = mn0; m1 = mn1;
        __syncthreads();

        #pragma unroll
        for (int ks = 0; ks < 64; ks += 8) {
            unsigned a[4];
            a[0] = __float_as_uint(Ps[r0    ][ks + gk]);
            a[1] = __float_as_uint(Ps[r0 + 8][ks + gk]);
            a[2] = __float_as_uint(Ps[r0    ][ks + gk + 4]);
            a[3] = __float_as_uint(Ps[r0 + 8][ks + gk + 4]);
            #pragma unroll
            for (int nt = 0; nt < 8; nt++) {
                unsigned bb[2];
                bb[0] = __float_as_uint(Vs[ks + gk    ][nt * 8 + gr]);
                bb[1] = __float_as_uint(Vs[ks + gk + 4][nt * 8 + gr]);
                mma_tf32(co[nt], a, bb);
            }
        }
    }

    const float inv0 = 1.f / l0, inv1 = 1.f / l1;
    float* o0 = O + (long)(b * 1024 + q0 + r0) * 512 + h * 64;
    float* o1 = o0 + 8 * 512;
    #pragma unroll
    for (int nt = 0; nt < 8; nt++) {
        int c = nt * 8 + gk * 2;
        *(float2*)(o0 + c) = make_float2(co[nt][0] * inv0, co[nt][1] * inv0);
        *(float2*)(o1 + c) = make_float2(co[nt][2] * inv1, co[nt][3] * inv1);
    }
}

// ---------------- LayerNorm: 0=plain, 2=stable ----------------
template<int MODE>
__global__ __launch_bounds__(256) void ln_kernel(
    const float* __restrict__ in, const float* __restrict__ gam,
    float* __restrict__ out, int C)
{
    __shared__ float sred[8];
    long row = blockIdx.x;
    const float* x = in + row * (long)C;
    int tid = threadIdx.x;
    bool two = (C > 256);
    float v0 = x[tid];
    float v1 = two ? x[tid + 256] : 0.f;

    if (MODE == 2) {
        float mx = two ? fmaxf(v0, v1) : v0;
        mx = blockMax(mx, sred);
        float inv = 1.0f / mx;
        v0 *= inv; v1 *= inv;
    }
    float s = blockSum(v0 + v1, sred);
    float mu = s / (float)C;
    float d0 = v0 - mu, d1 = v1 - mu;
    float sq = d0 * d0 + (two ? d1 * d1 : 0.f);
    sq = blockSum(sq, sred);
    float rstd = rsqrtf(sq / (float)C + 1e-5f);

    out[row * (long)C + tid] = d0 * rstd * gam[tid];
    if (two) out[row * (long)C + tid + 256] = d1 * rstd * gam[tid + 256];
}

// ---- fused: X = X + LN(T)*g1 ; XN = LN(X)*g2   (C = 512) ----
__global__ __launch_bounds__(256) void ln_res_ln(
    const float* __restrict__ T, const float* __restrict__ g1,
    const float* __restrict__ g2,
    float* __restrict__ X, float* __restrict__ XN)
{
    __shared__ float sred[8];
    long row = blockIdx.x;
    int tid = threadIdx.x;
    const float* t = T + row * 512;
    float v0 = t[tid], v1 = t[tid + 256];

    float s = blockSum(v0 + v1, sred);
    float mu = s * (1.0f / 512.0f);
    float d0 = v0 - mu, d1 = v1 - mu;
    float sq = blockSum(d0 * d0 + d1 * d1, sred);
    float rstd = rsqrtf(sq * (1.0f / 512.0f) + 1e-5f);

    float x0 = d0 * rstd * g1[tid]       + X[row * 512 + tid];
    float x1 = d1 * rstd * g1[tid + 256] + X[row * 512 + tid + 256];
    X[row * 512 + tid]       = x0;
    X[row * 512 + tid + 256] = x1;

    float s2 = blockSum(x0 + x1, sred);
    float mu2 = s2 * (1.0f / 512.0f);
    float e0 = x0 - mu2, e1 = x1 - mu2;
    float sq2 = blockSum(e0 * e0 + e1 * e1, sred);
    float rstd2 = rsqrtf(sq2 * (1.0f / 512.0f) + 1e-5f);

    XN[row * 512 + tid]       = e0 * rstd2 * g2[tid];
    XN[row * 512 + tid + 256] = e1 * rstd2 * g2[tid + 256];
}

// ---------------- KV prepare ----------------
template<bool ROT>
__global__ void prep_kv(const float* __restrict__ src, int ld, int koff,
                        const float* __restrict__ nullkv,
                        float* __restrict__ Kt, float* __restrict__ V, int srcN)
{
    int t = blockIdx.x;
    int b = blockIdx.y;
    int d = threadIdx.x;
    const float* kv = src + ((long)b * srcN + t) * ld + koff;
    float k = kv[d], v = kv[64 + d];
    V[((long)b * LDS_ + (t + 1)) * 64 + d] = v;
    float kr = k;
    if (ROT && d < 32) {
        int i = d & 15;
        float f = (float)t * powf(10000.0f, -(float)i * 0.0625f);
        float s, c; sincosf(f, &s, &c);
        float p = kv[(d < 16) ? d + 16 : d - 16];
        kr = (d < 16) ? (k * c - p * s) : (k * c + p * s);
    }
    Kt[((long)b * 64 + d) * LDS_ + (t + 1)] = kr;
    if (t == 0) {
        V[((long)b * LDS_) * 64 + d] = nullkv[64 + d];
        Kt[((long)b * 64 + d) * LDS_] = nullkv[d];
    }
    if (t < 15) {
        V[((long)b * LDS_ + srcN + 1 + t) * 64 + d] = 0.f;
    }
}

// ---------------- host helpers ----------------
static inline void gemm(const float* A, int lda,
                        const float* Bm, int ldb,
                        float* C, int ldc,
                        int M, int N, int K,
                        const float* Res = nullptr, int ldr = 0)
{
    dim3 g((N + 127) / 128, M / 128, 1);
    if (Res) tgemm_k<1, 0><<<g, 256>>>(A, lda, 0, 0, Bm, ldb, 0, 0,
                                       C, ldc, 0, 0, Res, ldr, N, K, 1);
    else     tgemm_k<0, 0><<<g, 256>>>(A, lda, 0, 0, Bm, ldb, 0, 0,
                                       C, ldc, 0, 0, nullptr, 0, N, K, 1);
}

#define FLASH_SMEM ((4 * 64 * 68 + 1024) * (int)sizeof(float))

extern "C" void kernel_launch(void* const* d_in, const int* in_sizes, int n_in,
                              void* d_out, int out_size)
{
    const float* x         = (const float*)d_in[0];
    const float* ctx       = (const float*)d_in[1];
    const float* rel_emb   = (const float*)d_in[2];
    const float* sa_norm_g = (const float*)d_in[3];
    const float* sa_wq     = (const float*)d_in[4];
    const float* sa_wkv    = (const float*)d_in[5];
    const float* sa_nkv    = (const float*)d_in[6];
    const float* sa_wo     = (const float*)d_in[7];
    const float* sa_out_g  = (const float*)d_in[8];
    const float* ca_norm_g = (const float*)d_in[9];
    const float* ca_ctx_g  = (const float*)d_in[10];
    const float* ca_wq     = (const float*)d_in[11];
    const float* ca_wkv    = (const float*)d_in[12];
    const float* ca_nkv    = (const float*)d_in[13];
    const float* ca_wo     = (const float*)d_in[14];
    const float* ca_out_g  = (const float*)d_in[15];
    const float* ff_norm_g = (const float*)d_in[16];
    const float* ff_w1     = (const float*)d_in[17];
    const float* ff_w2     = (const float*)d_in[18];
    const float* norm_g    = (const float*)d_in[19];

    float *pX, *pXN, *pQ, *pQKV, *pKVp, *pKt, *pV, *pO, *pT, *pH1, *pCTXN, *pW;
    cudaGetSymbolAddress((void**)&pX,    g_X);
    cudaGetSymbolAddress((void**)&pXN,   g_XN);
    cudaGetSymbolAddress((void**)&pQ,    g_Q);
    cudaGetSymbolAddress((void**)&pQKV,  g_QKV);
    cudaGetSymbolAddress((void**)&pKVp,  g_KVp);
    cudaGetSymbolAddress((void**)&pKt,   g_Kt);
    cudaGetSymbolAddress((void**)&pV,    g_V);
    cudaGetSymbolAddress((void**)&pO,    g_O);
    cudaGetSymbolAddress((void**)&pT,    g_T);
    cudaGetSymbolAddress((void**)&pH1,   g_H1);
    cudaGetSymbolAddress((void**)&pCTXN, g_CTXN);
    cudaGetSymbolAddress((void**)&pW,    g_Wqkv);

    cudaFuncSetAttribute(flash_attn<true>,
                         cudaFuncAttributeMaxDynamicSharedMemorySize, FLASH_SMEM);
    cudaFuncSetAttribute(flash_attn<false>,
                         cudaFuncAttributeMaxDynamicSharedMemorySize, FLASH_SMEM);

    cudaMemcpyAsync(pX, x, (size_t)Bsz * Nq * Dm * sizeof(float),
                    cudaMemcpyDeviceToDevice);
    pack_qkv<<<1920, 256>>>(sa_wq, sa_wkv, pW);

    for (int l = 0; l < Ll; l++) {
        // ===== self attention =====
        ln_kernel<0><<<4096, 256>>>(pX, sa_norm_g + l * 512, pXN, 512);
        gemm(pXN, 512, pW + (long)l * 512 * 640, 640, pQKV, 640, 4096, 640, 512);
        prep_kv<true><<<dim3(1024, 4), 64>>>(pQKV, 640, 512,
                                             sa_nkv + l * 128, pKt, pV, 1024);
        flash_attn<true><<<dim3(16, 8, 4), 128, FLASH_SMEM>>>(
            pQKV, 640, pKt, pV, pO, rel_emb, 1025);
        gemm(pO, 512, sa_wo + (long)l * 512 * 512, 512, pT, 512, 4096, 512, 512);
        // X += LN(T)*sa_out_g ; XN = LN(X)*ca_norm_g
        ln_res_ln<<<4096, 256>>>(pT, sa_out_g + l * 512, ca_norm_g + l * 512, pX, pXN);

        // ===== cross attention =====
        ln_kernel<0><<<2048, 256>>>(ctx, ca_ctx_g + l * 256, pCTXN, 256);
        gemm(pXN, 512, ca_wq + (long)l * 512 * 512, 512, pQ, 512, 4096, 512, 512);
        sgemm64_k<<<dim3(2, 32), 128>>>(pCTXN, 256,
                                        ca_wkv + (long)l * 256 * 128, 128,
                                        pKVp, 128, 256);
        prep_kv<false><<<dim3(512, 4), 64>>>(pKVp, 128, 0,
                                             ca_nkv + l * 128, pKt, pV, 512);
        flash_attn<false><<<dim3(16, 8, 4), 128, FLASH_SMEM>>>(
            pQ, 512, pKt, pV, pO, nullptr, 513);
        gemm(pO, 512, ca_wo + (long)l * 512 * 512, 512, pT, 512, 4096, 512, 512);
        // X += LN(T)*ca_out_g ; XN = LN(X)*ff_norm_g
        ln_res_ln<<<4096, 256>>>(pT, ca_out_g + l * 512, ff_norm_g + l * 512, pX, pXN);

        // ===== feed forward (gate fused into ff2 A-load) =====
        gemm(pXN, 512, ff_w1 + (long)l * 512 * 4096, 4096, pH1, 4096, 4096, 4096, 512);
        {
            dim3 g(4, 32, 1);
            tgemm_k<1, 1><<<g, 256>>>(pH1, 4096, 0, 0,
                                      ff_w2 + (long)l * 2048 * 512, 512, 0, 0,
                                      pX, 512, 0, 0, pX, 512, 512, 2048, 1);
        }
    }

    ln_kernel<2><<<4096, 256>>>(pX, norm_g, (float*)d_out, 512);
}

// round 12
// speedup vs baseline: 1.0849x; 1.0849x over previous
#include <cuda_runtime.h>
#include <math.h>

// ---------------- problem dims ----------------
#define Bsz 4
#define Nq  1024
#define Mctx 512
#define Dm  512
#define Pm  256
#define Hh  8
#define DHh 64
#define Ll  6
#define FIi 2048
#define LDS_ 1040

// ---------------- device scratch ----------------
__device__ float g_X   [(long)Bsz*Nq*Dm];
__device__ float g_XN  [(long)Bsz*Nq*Dm];
__device__ float g_Q   [(long)Bsz*Nq*Dm];
__device__ float g_QKV [(long)Bsz*Nq*640];
__device__ float g_O   [(long)Bsz*Nq*Dm];
__device__ float g_T   [(long)Bsz*Nq*Dm];
__device__ float g_KVp [(long)Bsz*Nq*128];
__device__ float g_Kt  [(long)Bsz*64*LDS_];
__device__ float g_V   [(long)Bsz*LDS_*64];
__device__ float g_H1  [(long)Bsz*Nq*2*FIi];
__device__ float g_G   [(long)Bsz*Nq*FIi];
__device__ float g_CTXN[(long)Bsz*Mctx*Pm];
__device__ float g_Wqkv[(long)Ll*Dm*640];

// ---------------- helpers ----------------
__device__ __forceinline__ float f2tf(float f) {
    unsigned u;
    asm("cvt.rna.tf32.f32 %0, %1;" : "=r"(u) : "f"(f));
    return __uint_as_float(u);
}

__device__ __forceinline__ void mma_tf32(float* d, const unsigned* a, const unsigned* b) {
    asm volatile(
        "mma.sync.aligned.m16n8k8.row.col.f32.tf32.tf32.f32 "
        "{%0,%1,%2,%3}, {%4,%5,%6,%7}, {%8,%9}, {%0,%1,%2,%3};"
        : "+f"(d[0]), "+f"(d[1]), "+f"(d[2]), "+f"(d[3])
        : "r"(a[0]), "r"(a[1]), "r"(a[2]), "r"(a[3]), "r"(b[0]), "r"(b[1]));
}

__device__ __forceinline__ float blockMax(float v, float* sred) {
    #pragma unroll
    for (int o = 16; o; o >>= 1) v = fmaxf(v, __shfl_xor_sync(0xffffffffu, v, o));
    int tid = threadIdx.x;
    if ((tid & 31) == 0) sred[tid >> 5] = v;
    __syncthreads();
    if (tid < 32) {
        float t = (tid < 8) ? sred[tid] : -3.4e38f;
        #pragma unroll
        for (int o = 4; o; o >>= 1) t = fmaxf(t, __shfl_xor_sync(0xffffffffu, t, o));
        if (tid == 0) sred[0] = t;
    }
    __syncthreads();
    float r = sred[0];
    __syncthreads();
    return r;
}

__device__ __forceinline__ float blockSum(float v, float* sred) {
    #pragma unroll
    for (int o = 16; o; o >>= 1) v += __shfl_xor_sync(0xffffffffu, v, o);
    int tid = threadIdx.x;
    if ((tid & 31) == 0) sred[tid >> 5] = v;
    __syncthreads();
    if (tid < 32) {
        float t = (tid < 8) ? sred[tid] : 0.f;
        #pragma unroll
        for (int o = 4; o; o >>= 1) t += __shfl_xor_sync(0xffffffffu, t, o);
        if (tid == 0) sred[0] = t;
    }
    __syncthreads();
    float r = sred[0];
    __syncthreads();
    return r;
}

// ---------------- weight pack: W[l][k][0..639] = [wq | wkv] ----------------
__global__ __launch_bounds__(256) void pack_qkv(
    const float* __restrict__ wq, const float* __restrict__ wkv,
    float* __restrict__ W)
{
    long i4 = (long)blockIdx.x * 256 + threadIdx.x;
    long c4 = i4 % 160, rk = i4 / 160;
    float4 v;
    if (c4 < 128) v = *(const float4*)(wq + rk * 512 + c4 * 4);
    else          v = *(const float4*)(wkv + rk * 128 + (c4 - 128) * 4);
    *(float4*)(W + rk * 640 + c4 * 4) = v;
}

// ---------------- tf32 tensor-core GEMM: C = A @ B (+Res) ----------------
template<int FUSE>
__global__ __launch_bounds__(256, 2) void tgemm_k(
    const float* __restrict__ A, int lda,
    const float* __restrict__ Bm, int ldb,
    float* __restrict__ C, int ldc,
    const float* __restrict__ Res, int ldr,
    int N, int K)
{
    __shared__ float As[2][128][20];
    __shared__ float Bs[2][16][136];

    const int tid  = threadIdx.x;
    const int lane = tid & 31;
    const int warp = tid >> 5;
    const int wm = warp >> 2;
    const int wn = warp & 3;
    const int row0 = blockIdx.y << 7;
    const int col0 = blockIdx.x << 7;

    const int am = tid >> 2;
    const int ak = (tid & 3) << 2;
    const int bk = tid >> 5;
    const int bn = (tid & 31) << 2;

    float acc[4][4][4];
    #pragma unroll
    for (int mi = 0; mi < 4; mi++)
        #pragma unroll
        for (int ni = 0; ni < 4; ni++)
            #pragma unroll
            for (int c = 0; c < 4; c++) acc[mi][ni][c] = 0.f;

    {
        #pragma unroll
        for (int it = 0; it < 2; it++) {
            int m = am + it * 64;
            float4 av = *(const float4*)(A + (long)(row0 + m) * lda + ak);
            As[0][m][ak + 0] = f2tf(av.x);
            As[0][m][ak + 1] = f2tf(av.y);
            As[0][m][ak + 2] = f2tf(av.z);
            As[0][m][ak + 3] = f2tf(av.w);
        }
        #pragma unroll
        for (int it = 0; it < 2; it++) {
            int k = bk + it * 8;
            int col = col0 + bn;
            float4 bv = make_float4(0.f, 0.f, 0.f, 0.f);
            if (col < N) bv = *(const float4*)(Bm + (long)k * ldb + col);
            Bs[0][k][bn + 0] = f2tf(bv.x);
            Bs[0][k][bn + 1] = f2tf(bv.y);
            Bs[0][k][bn + 2] = f2tf(bv.z);
            Bs[0][k][bn + 3] = f2tf(bv.w);
        }
    }
    __syncthreads();

    const int gr = lane >> 2;
    const int gk = lane & 3;

    int buf = 0;
    for (int k0 = 0; k0 < K; k0 += 16) {
        bool hasNext = (k0 + 16 < K);
        float4 pa0, pa1, pb0, pb1;
        if (hasNext) {
            pa0 = *(const float4*)(A + (long)(row0 + am)      * lda + k0 + 16 + ak);
            pa1 = *(const float4*)(A + (long)(row0 + am + 64) * lda + k0 + 16 + ak);
            int col = col0 + bn;
            pb0 = make_float4(0.f, 0.f, 0.f, 0.f);
            pb1 = pb0;
            if (col < N) {
                pb0 = *(const float4*)(Bm + (long)(k0 + 16 + bk)     * ldb + col);
                pb1 = *(const float4*)(Bm + (long)(k0 + 16 + bk + 8) * ldb + col);
            }
        }

        #pragma unroll
        for (int ks = 0; ks < 16; ks += 8) {
            unsigned a[4][4], b[4][2];
            #pragma unroll
            for (int mi = 0; mi < 4; mi++) {
                int r = wm * 64 + mi * 16 + gr;
                a[mi][0] = __float_as_uint(As[buf][r    ][ks + gk]);
                a[mi][1] = __float_as_uint(As[buf][r + 8][ks + gk]);
                a[mi][2] = __float_as_uint(As[buf][r    ][ks + gk + 4]);
                a[mi][3] = __float_as_uint(As[buf][r + 8][ks + gk + 4]);
            }
            #pragma unroll
            for (int ni = 0; ni < 4; ni++) {
                int c = wn * 32 + ni * 8 + gr;
                b[ni][0] = __float_as_uint(Bs[buf][ks + gk    ][c]);
                b[ni][1] = __float_as_uint(Bs[buf][ks + gk + 4][c]);
            }
            #pragma unroll
            for (int mi = 0; mi < 4; mi++)
                #pragma unroll
                for (int ni = 0; ni < 4; ni++)
                    mma_tf32(acc[mi][ni], a[mi], b[ni]);
        }

        if (hasNext) {
            As[buf ^ 1][am][ak + 0] = f2tf(pa0.x);
            As[buf ^ 1][am][ak + 1] = f2tf(pa0.y);
            As[buf ^ 1][am][ak + 2] = f2tf(pa0.z);
            As[buf ^ 1][am][ak + 3] = f2tf(pa0.w);
            As[buf ^ 1][am + 64][ak + 0] = f2tf(pa1.x);
            As[buf ^ 1][am + 64][ak + 1] = f2tf(pa1.y);
            As[buf ^ 1][am + 64][ak + 2] = f2tf(pa1.z);
            As[buf ^ 1][am + 64][ak + 3] = f2tf(pa1.w);
            Bs[buf ^ 1][bk][bn + 0] = f2tf(pb0.x);
            Bs[buf ^ 1][bk][bn + 1] = f2tf(pb0.y);
            Bs[buf ^ 1][bk][bn + 2] = f2tf(pb0.z);
            Bs[buf ^ 1][bk][bn + 3] = f2tf(pb0.w);
            Bs[buf ^ 1][bk + 8][bn + 0] = f2tf(pb1.x);
            Bs[buf ^ 1][bk + 8][bn + 1] = f2tf(pb1.y);
            Bs[buf ^ 1][bk + 8][bn + 2] = f2tf(pb1.z);
            Bs[buf ^ 1][bk + 8][bn + 3] = f2tf(pb1.w);
        }
        __syncthreads();
        buf ^= 1;
    }

    bool fullN = (col0 + 128 <= N);
    #pragma unroll
    for (int mi = 0; mi < 4; mi++) {
        #pragma unroll
        for (int ni = 0; ni < 4; ni++) {
            int r  = row0 + wm * 64 + mi * 16 + gr;
            int cc = col0 + wn * 32 + ni * 8 + gk * 2;
            float* c0p = C + (long)r * ldc + cc;
            float* c2p = C + (long)(r + 8) * ldc + cc;
            float v0 = acc[mi][ni][0], v1 = acc[mi][ni][1];
            float v2 = acc[mi][ni][2], v3 = acc[mi][ni][3];
            if (FUSE) {
                const float* r0p = Res + (long)r * ldr + cc;
                const float* r2p = Res + (long)(r + 8) * ldr + cc;
                if (fullN) {
                    float2 q0 = *(const float2*)r0p;
                    float2 q2 = *(const float2*)r2p;
                    v0 += q0.x; v1 += q0.y; v2 += q2.x; v3 += q2.y;
                } else {
                    if (cc     < N) { v0 += r0p[0]; v2 += r2p[0]; }
                    if (cc + 1 < N) { v1 += r0p[1]; v3 += r2p[1]; }
                }
            }
            if (fullN) {
                *(float2*)c0p = make_float2(v0, v1);
                *(float2*)c2p = make_float2(v2, v3);
            } else {
                if (cc     < N) { c0p[0] = v0; c2p[0] = v2; }
                if (cc + 1 < N) { c0p[1] = v1; c2p[1] = v3; }
            }
        }
    }
}

// ---------------- small 64x64-tile tf32 GEMM ----------------
__global__ __launch_bounds__(128) void sgemm64_k(
    const float* __restrict__ A, int lda,
    const float* __restrict__ Bm, int ldb,
    float* __restrict__ C, int ldc, int K)
{
    __shared__ float As[64][20];
    __shared__ float Bs[16][72];
    const int tid = threadIdx.x;
    const int lane = tid & 31, warp = tid >> 5;
    const int wm = warp >> 1, wn = warp & 1;
    const int row0 = blockIdx.y << 6, col0 = blockIdx.x << 6;
    const int gr = lane >> 2, gk = lane & 3;

    const int am = tid >> 1, ak = (tid & 1) * 8;
    const int bkr = tid >> 3, bc = (tid & 7) * 8;

    float acc[2][4][4];
    #pragma unroll
    for (int mi = 0; mi < 2; mi++)
        #pragma unroll
        for (int ni = 0; ni < 4; ni++)
            #pragma unroll
            for (int e = 0; e < 4; e++) acc[mi][ni][e] = 0.f;

    for (int k0 = 0; k0 < K; k0 += 16) {
        float4 a0 = *(const float4*)(A + (long)(row0 + am) * lda + k0 + ak);
        float4 a1 = *(const float4*)(A + (long)(row0 + am) * lda + k0 + ak + 4);
        As[am][ak + 0] = f2tf(a0.x); As[am][ak + 1] = f2tf(a0.y);
        As[am][ak + 2] = f2tf(a0.z); As[am][ak + 3] = f2tf(a0.w);
        As[am][ak + 4] = f2tf(a1.x); As[am][ak + 5] = f2tf(a1.y);
        As[am][ak + 6] = f2tf(a1.z); As[am][ak + 7] = f2tf(a1.w);
        float4 b0 = *(const float4*)(Bm + (long)(k0 + bkr) * ldb + col0 + bc);
        float4 b1 = *(const float4*)(Bm + (long)(k0 + bkr) * ldb + col0 + bc + 4);
        Bs[bkr][bc + 0] = f2tf(b0.x); Bs[bkr][bc + 1] = f2tf(b0.y);
        Bs[bkr][bc + 2] = f2tf(b0.z); Bs[bkr][bc + 3] = f2tf(b0.w);
        Bs[bkr][bc + 4] = f2tf(b1.x); Bs[bkr][bc + 5] = f2tf(b1.y);
        Bs[bkr][bc + 6] = f2tf(b1.z); Bs[bkr][bc + 7] = f2tf(b1.w);
        __syncthreads();
        #pragma unroll
        for (int ks = 0; ks < 16; ks += 8) {
            unsigned a[2][4], b[4][2];
            #pragma unroll
            for (int mi = 0; mi < 2; mi++) {
                int r = wm * 32 + mi * 16 + gr;
                a[mi][0] = __float_as_uint(As[r    ][ks + gk]);
                a[mi][1] = __float_as_uint(As[r + 8][ks + gk]);
                a[mi][2] = __float_as_uint(As[r    ][ks + gk + 4]);
                a[mi][3] = __float_as_uint(As[r + 8][ks + gk + 4]);
            }
            #pragma unroll
            for (int ni = 0; ni < 4; ni++) {
                int c = wn * 32 + ni * 8 + gr;
                b[ni][0] = __float_as_uint(Bs[ks + gk    ][c]);
                b[ni][1] = __float_as_uint(Bs[ks + gk + 4][c]);
            }
            #pragma unroll
            for (int mi = 0; mi < 2; mi++)
                #pragma unroll
                for (int ni = 0; ni < 4; ni++)
                    mma_tf32(acc[mi][ni], a[mi], b[ni]);
        }
        __syncthreads();
    }

    #pragma unroll
    for (int mi = 0; mi < 2; mi++)
        #pragma unroll
        for (int ni = 0; ni < 4; ni++) {
            int r  = row0 + wm * 32 + mi * 16 + gr;
            int cc = col0 + wn * 32 + ni * 8 + gk * 2;
            *(float2*)(C + (long)r * ldc + cc)       = make_float2(acc[mi][ni][0], acc[mi][ni][1]);
            *(float2*)(C + (long)(r + 8) * ldc + cc) = make_float2(acc[mi][ni][2], acc[mi][ni][3]);
        }
}

// ---------------- fused flash attention ----------------
template<bool CAUSAL>
__global__ __launch_bounds__(128) void flash_attn(
    const float* __restrict__ Q, int ldq,
    const float* __restrict__ Kt,
    const float* __restrict__ V,
    float* __restrict__ O,
    const float* __restrict__ emb,
    int Ltot)
{
    extern __shared__ float sm[];
    float (*Qs)[68] = (float(*)[68])sm;
    float (*Ks)[68] = (float(*)[68])(sm + 64 * 68);
    float (*Vs)[68] = (float(*)[68])(sm + 2 * 64 * 68);
    float (*Ps)[68] = (float(*)[68])(sm + 3 * 64 * 68);
    float* biasLUT  = sm + 4 * 64 * 68;

    const int qi = blockIdx.x, h = blockIdx.y, b = blockIdx.z;
    const int q0 = qi << 6;
    const int tid = threadIdx.x;
    const int warp = tid >> 5, lane = tid & 31;
    const int gr = lane >> 2, gk = lane & 3;
    const int r0 = (warp << 4) + gr;

    if (CAUSAL) {
        for (int n = tid; n < 1024; n += 128) {
            int bucket;
            if (n < 16) bucket = n;
            else {
                int lg = (int)(logf((float)n * 0.0625f) * 7.69486038f);
                bucket = min(16 + lg, 31);
            }
            biasLUT[n] = emb[bucket * 8 + h];
        }
    }

    {
        const int row = tid >> 1, half = tid & 1;
        const float* srcp = Q + (long)(b * 1024 + q0 + row) * ldq + h * 64 + half * 32;
        float vals[32];
        #pragma unroll
        for (int e = 0; e < 8; e++)
            *(float4*)&vals[e * 4] = *(const float4*)(srcp + e * 4);
        if (CAUSAL && half == 0) {
            int t = q0 + row;
            #pragma unroll
            for (int i = 0; i < 16; i++) {
                float f = (float)t * powf(10000.0f, -(float)i * 0.0625f);
                float s, c; sincosf(f, &s, &c);
                float x1 = vals[i], x2 = vals[i + 16];
                vals[i]      = x1 * c - x2 * s;
                vals[i + 16] = x2 * c + x1 * s;
            }
        }
        #pragma unroll
        for (int i = 0; i < 32; i++)
            Qs[row][half * 32 + i] = f2tf(vals[i] * 0.125f);
    }

    float m0 = -1e30f, m1 = -1e30f, l0 = 0.f, l1 = 0.f;
    float co[8][4];
    #pragma unroll
    for (int nt = 0; nt < 8; nt++)
        #pragma unroll
        for (int e = 0; e < 4; e++) co[nt][e] = 0.f;

    const int ntiles = CAUSAL ? (qi + 2) : ((Ltot + 63) >> 6);

    for (int t = 0; t < ntiles; t++) {
        const int j0 = t << 6;
        __syncthreads();
        const float* ksrc = Kt + (long)b * 64 * LDS_ + j0;
        const float* vsrc = V + ((long)b * LDS_ + j0) * 64;
        if (j0 + 64 <= Ltot) {
            #pragma unroll
            for (int it = 0; it < 8; it++) {
                int idx = tid + it * 128;
                int r = idx >> 4, c4 = (idx & 15) << 2;
                float4 k4 = *(const float4*)(ksrc + (long)r * LDS_ + c4);
                Ks[r][c4 + 0] = f2tf(k4.x); Ks[r][c4 + 1] = f2tf(k4.y);
                Ks[r][c4 + 2] = f2tf(k4.z); Ks[r][c4 + 3] = f2tf(k4.w);
                float4 vv = *(const float4*)(vsrc + (long)r * 64 + c4);
                Vs[r][c4 + 0] = f2tf(vv.x); Vs[r][c4 + 1] = f2tf(vv.y);
                Vs[r][c4 + 2] = f2tf(vv.z); Vs[r][c4 + 3] = f2tf(vv.w);
            }
        } else {
            #pragma unroll
            for (int it = 0; it < 8; it++) {
                int idx = tid + it * 128;
                int r = idx >> 4, c4 = (idx & 15) << 2;
                #pragma unroll
                for (int e = 0; e < 4; e++) {
                    int jk = j0 + c4 + e;
                    Ks[r][c4 + e] = (jk < Ltot) ? f2tf(ksrc[(long)r * LDS_ + c4 + e]) : 0.f;
                }
                int jv = j0 + r;
                #pragma unroll
                for (int e = 0; e < 4; e++)
                    Vs[r][c4 + e] = (jv < Ltot) ? f2tf(vsrc[(long)r * 64 + c4 + e]) : 0.f;
            }
        }
        __syncthreads();

        float cs[8][4];
        #pragma unroll
        for (int nt = 0; nt < 8; nt++)
            #pragma unroll
            for (int e = 0; e < 4; e++) cs[nt][e] = 0.f;
        #pragma unroll
        for (int ks = 0; ks < 64; ks += 8) {
            unsigned a[4];
            a[0] = __float_as_uint(Qs[r0    ][ks + gk]);
            a[1] = __float_as_uint(Qs[r0 + 8][ks + gk]);
            a[2] = __float_as_uint(Qs[r0    ][ks + gk + 4]);
            a[3] = __float_as_uint(Qs[r0 + 8][ks + gk + 4]);
            #pragma unroll
            for (int nt = 0; nt < 8; nt++) {
                unsigned bb[2];
                bb[0] = __float_as_uint(Ks[ks + gk    ][nt * 8 + gr]);
                bb[1] = __float_as_uint(Ks[ks + gk + 4][nt * 8 + gr]);
                mma_tf32(cs[nt], a, bb);
            }
        }

        const int i0 = q0 + r0, i1 = i0 + 8;
        float tm0 = -1e30f, tm1 = -1e30f;
        #pragma unroll
        for (int nt = 0; nt < 8; nt++) {
            #pragma unroll
            for (int e = 0; e < 2; e++) {
                int jj = j0 + nt * 8 + gk * 2 + e;
                float s0 = cs[nt][e], s1 = cs[nt][2 + e];
                if (CAUSAL) {
                    s0 = (jj <= i0 + 1) ? s0 + biasLUT[max(i0 - jj, 0)] : -1e30f;
                    s1 = (jj <= i1 + 1) ? s1 + biasLUT[max(i1 - jj, 0)] : -1e30f;
                } else {
                    if (jj >= Ltot) { s0 = -1e30f; s1 = -1e30f; }
                }
                cs[nt][e] = s0; cs[nt][2 + e] = s1;
                tm0 = fmaxf(tm0, s0); tm1 = fmaxf(tm1, s1);
            }
        }
        tm0 = fmaxf(tm0, __shfl_xor_sync(0xffffffffu, tm0, 1));
        tm0 = fmaxf(tm0, __shfl_xor_sync(0xffffffffu, tm0, 2));
        tm1 = fmaxf(tm1, __shfl_xor_sync(0xffffffffu, tm1, 1));
        tm1 = fmaxf(tm1, __shfl_xor_sync(0xffffffffu, tm1, 2));

        float mn0 = fmaxf(m0, tm0), mn1 = fmaxf(m1, tm1);
        float sc0 = __expf(m0 - mn0), sc1 = __expf(m1 - mn1);
        float ps0 = 0.f, ps1 = 0.f;
        #pragma unroll
        for (int nt = 0; nt < 8; nt++) {
            float p00 = __expf(cs[nt][0] - mn0);
            float p01 = __expf(cs[nt][1] - mn0);
            float p10 = __expf(cs[nt][2] - mn1);
            float p11 = __expf(cs[nt][3] - mn1);
            ps0 += p00 + p01; ps1 += p10 + p11;
            int c = nt * 8 + gk * 2;
            *(float2*)&Ps[r0    ][c] = make_float2(f2tf(p00), f2tf(p01));
            *(float2*)&Ps[r0 + 8][c] = make_float2(f2tf(p10), f2tf(p11));
            co[nt][0] *= sc0; co[nt][1] *= sc0;
            co[nt][2] *= sc1; co[nt][3] *= sc1;
        }
        ps0 += __shfl_xor_sync(0xffffffffu, ps0, 1);
        ps0 += __shfl_xor_sync(0xffffffffu, ps0, 2);
        ps1 += __shfl_xor_sync(0xffffffffu, ps1, 1);
        ps1 += __shfl_xor_sync(0xffffffffu, ps1, 2);
        l0 = l0 * sc0 + ps0; l1 = l1 * sc1 + ps1;
        m0 = mn0; m1 = mn1;
        __syncthreads();

        #pragma unroll
        for (int ks = 0; ks < 64; ks += 8) {
            unsigned a[4];
            a[0] = __float_as_uint(Ps[r0    ][ks + gk]);
            a[1] = __float_as_uint(Ps[r0 + 8][ks + gk]);
            a[2] = __float_as_uint(Ps[r0    ][ks + gk + 4]);
            a[3] = __float_as_uint(Ps[r0 + 8][ks + gk + 4]);
            #pragma unroll
            for (int nt = 0; nt < 8; nt++) {
                unsigned bb[2];
                bb[0] = __float_as_uint(Vs[ks + gk    ][nt * 8 + gr]);
                bb[1] = __float_as_uint(Vs[ks + gk + 4][nt * 8 + gr]);
                mma_tf32(co[nt], a, bb);
            }
        }
    }

    const float inv0 = 1.f / l0, inv1 = 1.f / l1;
    float* o0 = O + (long)(b * 1024 + q0 + r0) * 512 + h * 64;
    float* o1 = o0 + 8 * 512;
    #pragma unroll
    for (int nt = 0; nt < 8; nt++) {
        int c = nt * 8 + gk * 2;
        *(float2*)(o0 + c) = make_float2(co[nt][0] * inv0, co[nt][1] * inv0);
        *(float2*)(o1 + c) = make_float2(co[nt][2] * inv1, co[nt][3] * inv1);
    }
}

// ---------------- LayerNorm: 0=plain, 2=stable ----------------
template<int MODE>
__global__ __launch_bounds__(256) void ln_kernel(
    const float* __restrict__ in, const float* __restrict__ gam,
    float* __restrict__ out, int C)
{
    __shared__ float sred[8];
    long row = blockIdx.x;
    const float* x = in + row * (long)C;
    int tid = threadIdx.x;
    bool two = (C > 256);
    float v0 = x[tid];
    float v1 = two ? x[tid + 256] : 0.f;

    if (MODE == 2) {
        float mx = two ? fmaxf(v0, v1) : v0;
        mx = blockMax(mx, sred);
        float inv = 1.0f / mx;
        v0 *= inv; v1 *= inv;
    }
    float s = blockSum(v0 + v1, sred);
    float mu = s / (float)C;
    float d0 = v0 - mu, d1 = v1 - mu;
    float sq = d0 * d0 + (two ? d1 * d1 : 0.f);
    sq = blockSum(sq, sred);
    float rstd = rsqrtf(sq / (float)C + 1e-5f);

    out[row * (long)C + tid] = d0 * rstd * gam[tid];
    if (two) out[row * (long)C + tid + 256] = d1 * rstd * gam[tid + 256];
}

// ---- fused: X = X + LN(T)*g1 ; XN = LN(X)*g2   (C = 512) ----
__global__ __launch_bounds__(256) void ln_res_ln(
    const float* __restrict__ T, const float* __restrict__ g1,
    const float* __restrict__ g2,
    float* __restrict__ X, float* __restrict__ XN)
{
    __shared__ float sred[8];
    long row = blockIdx.x;
    int tid = threadIdx.x;
    const float* t = T + row * 512;
    float v0 = t[tid], v1 = t[tid + 256];

    float s = blockSum(v0 + v1, sred);
    float mu = s * (1.0f / 512.0f);
    float d0 = v0 - mu, d1 = v1 - mu;
    float sq = blockSum(d0 * d0 + d1 * d1, sred);
    float rstd = rsqrtf(sq * (1.0f / 512.0f) + 1e-5f);

    float x0 = d0 * rstd * g1[tid]       + X[row * 512 + tid];
    float x1 = d1 * rstd * g1[tid + 256] + X[row * 512 + tid + 256];
    X[row * 512 + tid]       = x0;
    X[row * 512 + tid + 256] = x1;

    float s2 = blockSum(x0 + x1, sred);
    float mu2 = s2 * (1.0f / 512.0f);
    float e0 = x0 - mu2, e1 = x1 - mu2;
    float sq2 = blockSum(e0 * e0 + e1 * e1, sred);
    float rstd2 = rsqrtf(sq2 * (1.0f / 512.0f) + 1e-5f);

    XN[row * 512 + tid]       = e0 * rstd2 * g2[tid];
    XN[row * 512 + tid + 256] = e1 * rstd2 * g2[tid + 256];
}

// ---------------- KV prepare ----------------
template<bool ROT>
__global__ void prep_kv(const float* __restrict__ src, int ld, int koff,
                        const float* __restrict__ nullkv,
                        float* __restrict__ Kt, float* __restrict__ V, int srcN)
{
    int t = blockIdx.x;
    int b = blockIdx.y;
    int d = threadIdx.x;
    const float* kv = src + ((long)b * srcN + t) * ld + koff;
    float k = kv[d], v = kv[64 + d];
    V[((long)b * LDS_ + (t + 1)) * 64 + d] = v;
    float kr = k;
    if (ROT && d < 32) {
        int i = d & 15;
        float f = (float)t * powf(10000.0f, -(float)i * 0.0625f);
        float s, c; sincosf(f, &s, &c);
        float p = kv[(d < 16) ? d + 16 : d - 16];
        kr = (d < 16) ? (k * c - p * s) : (k * c + p * s);
    }
    Kt[((long)b * 64 + d) * LDS_ + (t + 1)] = kr;
    if (t == 0) {
        V[((long)b * LDS_) * 64 + d] = nullkv[64 + d];
        Kt[((long)b * 64 + d) * LDS_] = nullkv[d];
    }
    if (t < 15) {
        V[((long)b * LDS_ + srcN + 1 + t) * 64 + d] = 0.f;
    }
}

// ---------------- FFN gate ----------------
__global__ __launch_bounds__(256) void silu_gate(const float* __restrict__ H1,
                                                 float* __restrict__ G)
{
    long idx = (long)blockIdx.x * 256 + threadIdx.x;
    long r = idx >> 11, c = idx & 2047;
    float hh = H1[r * 4096 + c];
    float gt = H1[r * 4096 + 2048 + c];
    G[idx] = hh * gt / (1.0f + expf(-gt));
}

// ---------------- host helpers ----------------
static inline void gemm(const float* A, int lda,
                        const float* Bm, int ldb,
                        float* C, int ldc,
                        int M, int N, int K,
                        const float* Res = nullptr, int ldr = 0)
{
    dim3 g((N + 127) / 128, M / 128, 1);
    if (Res) tgemm_k<1><<<g, 256>>>(A, lda, Bm, ldb, C, ldc, Res, ldr, N, K);
    else     tgemm_k<0><<<g, 256>>>(A, lda, Bm, ldb, C, ldc, nullptr, 0, N, K);
}

#define FLASH_SMEM ((4 * 64 * 68 + 1024) * (int)sizeof(float))

extern "C" void kernel_launch(void* const* d_in, const int* in_sizes, int n_in,
                              void* d_out, int out_size)
{
    const float* x         = (const float*)d_in[0];
    const float* ctx       = (const float*)d_in[1];
    const float* rel_emb   = (const float*)d_in[2];
    const float* sa_norm_g = (const float*)d_in[3];
    const float* sa_wq     = (const float*)d_in[4];
    const float* sa_wkv    = (const float*)d_in[5];
    const float* sa_nkv    = (const float*)d_in[6];
    const float* sa_wo     = (const float*)d_in[7];
    const float* sa_out_g  = (const float*)d_in[8];
    const float* ca_norm_g = (const float*)d_in[9];
    const float* ca_ctx_g  = (const float*)d_in[10];
    const float* ca_wq     = (const float*)d_in[11];
    const float* ca_wkv    = (const float*)d_in[12];
    const float* ca_nkv    = (const float*)d_in[13];
    const float* ca_wo     = (const float*)d_in[14];
    const float* ca_out_g  = (const float*)d_in[15];
    const float* ff_norm_g = (const float*)d_in[16];
    const float* ff_w1     = (const float*)d_in[17];
    const float* ff_w2     = (const float*)d_in[18];
    const float* norm_g    = (const float*)d_in[19];

    float *pX, *pXN, *pQ, *pQKV, *pKVp, *pKt, *pV, *pO, *pT, *pH1, *pG, *pCTXN, *pW;
    cudaGetSymbolAddress((void**)&pX,    g_X);
    cudaGetSymbolAddress((void**)&pXN,   g_XN);
    cudaGetSymbolAddress((void**)&pQ,    g_Q);
    cudaGetSymbolAddress((void**)&pQKV,  g_QKV);
    cudaGetSymbolAddress((void**)&pKVp,  g_KVp);
    cudaGetSymbolAddress((void**)&pKt,   g_Kt);
    cudaGetSymbolAddress((void**)&pV,    g_V);
    cudaGetSymbolAddress((void**)&pO,    g_O);
    cudaGetSymbolAddress((void**)&pT,    g_T);
    cudaGetSymbolAddress((void**)&pH1,   g_H1);
    cudaGetSymbolAddress((void**)&pG,    g_G);
    cudaGetSymbolAddress((void**)&pCTXN, g_CTXN);
    cudaGetSymbolAddress((void**)&pW,    g_Wqkv);

    cudaFuncSetAttribute(flash_attn<true>,
                         cudaFuncAttributeMaxDynamicSharedMemorySize, FLASH_SMEM);
    cudaFuncSetAttribute(flash_attn<false>,
                         cudaFuncAttributeMaxDynamicSharedMemorySize, FLASH_SMEM);

    cudaMemcpyAsync(pX, x, (size_t)Bsz * Nq * Dm * sizeof(float),
                    cudaMemcpyDeviceToDevice);
    pack_qkv<<<1920, 256>>>(sa_wq, sa_wkv, pW);

    for (int l = 0; l < Ll; l++) {
        // ===== self attention =====
        ln_kernel<0><<<4096, 256>>>(pX, sa_norm_g + l * 512, pXN, 512);
        gemm(pXN, 512, pW + (long)l * 512 * 640, 640, pQKV, 640, 4096, 640, 512);
        prep_kv<true><<<dim3(1024, 4), 64>>>(pQKV, 640, 512,
                                             sa_nkv + l * 128, pKt, pV, 1024);
        flash_attn<true><<<dim3(16, 8, 4), 128, FLASH_SMEM>>>(
            pQKV, 640, pKt, pV, pO, rel_emb, 1025);
        gemm(pO, 512, sa_wo + (long)l * 512 * 512, 512, pT, 512, 4096, 512, 512);
        ln_res_ln<<<4096, 256>>>(pT, sa_out_g + l * 512, ca_norm_g + l * 512, pX, pXN);

        // ===== cross attention =====
        ln_kernel<0><<<2048, 256>>>(ctx, ca_ctx_g + l * 256, pCTXN, 256);
        gemm(pXN, 512, ca_wq + (long)l * 512 * 512, 512, pQ, 512, 4096, 512, 512);
        sgemm64_k<<<dim3(2, 32), 128>>>(pCTXN, 256,
                                        ca_wkv + (long)l * 256 * 128, 128,
                                        pKVp, 128, 256);
        prep_kv<false><<<dim3(512, 4), 64>>>(pKVp, 128, 0,
                                             ca_nkv + l * 128, pKt, pV, 512);
        flash_attn<false><<<dim3(16, 8, 4), 128, FLASH_SMEM>>>(
            pQ, 512, pKt, pV, pO, nullptr, 513);
        gemm(pO, 512, ca_wo + (long)l * 512 * 512, 512, pT, 512, 4096, 512, 512);
        ln_res_ln<<<4096, 256>>>(pT, ca_out_g + l * 512, ff_norm_g + l * 512, pX, pXN);

        // ===== feed forward =====
        gemm(pXN, 512, ff_w1 + (long)l * 512 * 4096, 4096, pH1, 4096, 4096, 4096, 512);
        silu_gate<<<32768, 256>>>(pH1, pG);
        gemm(pG, 2048, ff_w2 + (long)l * 2048 * 512, 512, pX, 512, 4096, 512, 2048, pX, 512);
    }

    ln_kernel<2><<<4096, 256>>>(pX, norm_g, (float*)d_out, 512);
}

// round 13
// speedup vs baseline: 1.1621x; 1.0711x over previous
#include <cuda_runtime.h>
#include <math.h>

// ---------------- problem dims ----------------
#define Bsz 4
#define Nq  1024
#define Mctx 512
#define Dm  512
#define Pm  256
#define Hh  8
#define DHh 64
#define Ll  6
#define FIi 2048
#define LDS_ 1040

// ---------------- device scratch ----------------
__device__ float g_X   [(long)Bsz*Nq*Dm];
__device__ float g_XN  [(long)Bsz*Nq*Dm];
__device__ float g_Q   [(long)Bsz*Nq*Dm];
__device__ float g_QKV [(long)Bsz*Nq*640];
__device__ float g_O   [(long)Bsz*Nq*Dm];
__device__ float g_T   [(long)Bsz*Nq*Dm];
__device__ float g_KVp [(long)Bsz*Nq*128];
__device__ float g_Kt  [(long)Bsz*64*LDS_];
__device__ float g_V   [(long)Bsz*LDS_*64];
__device__ float g_H1  [(long)Bsz*Nq*2*FIi];
__device__ float g_G   [(long)Bsz*Nq*FIi];
__device__ float g_CTXN[(long)Bsz*Mctx*Pm];
__device__ float g_Wqkv[(long)Ll*Dm*640];

// ---------------- helpers ----------------
__device__ __forceinline__ float f2tf(float f) {
    unsigned u;
    asm("cvt.rna.tf32.f32 %0, %1;" : "=r"(u) : "f"(f));
    return __uint_as_float(u);
}

__device__ __forceinline__ unsigned f2tfu(float f) {
    unsigned u;
    asm("cvt.rna.tf32.f32 %0, %1;" : "=r"(u) : "f"(f));
    return u;
}

__device__ __forceinline__ void mma_tf32(float* d, const unsigned* a, const unsigned* b) {
    asm volatile(
        "mma.sync.aligned.m16n8k8.row.col.f32.tf32.tf32.f32 "
        "{%0,%1,%2,%3}, {%4,%5,%6,%7}, {%8,%9}, {%0,%1,%2,%3};"
        : "+f"(d[0]), "+f"(d[1]), "+f"(d[2]), "+f"(d[3])
        : "r"(a[0]), "r"(a[1]), "r"(a[2]), "r"(a[3]), "r"(b[0]), "r"(b[1]));
}

__device__ __forceinline__ void cp16(void* smem_dst, const void* gsrc) {
    unsigned s = (unsigned)__cvta_generic_to_shared(smem_dst);
    asm volatile("cp.async.ca.shared.global [%0], [%1], 16;" :: "r"(s), "l"(gsrc));
}
#define CP_COMMIT()  asm volatile("cp.async.commit_group;")
#define CP_WAIT2()   asm volatile("cp.async.wait_group 2;")

__device__ __forceinline__ float blockMax(float v, float* sred) {
    #pragma unroll
    for (int o = 16; o; o >>= 1) v = fmaxf(v, __shfl_xor_sync(0xffffffffu, v, o));
    int tid = threadIdx.x;
    if ((tid & 31) == 0) sred[tid >> 5] = v;
    __syncthreads();
    if (tid < 32) {
        float t = (tid < 8) ? sred[tid] : -3.4e38f;
        #pragma unroll
        for (int o = 4; o; o >>= 1) t = fmaxf(t, __shfl_xor_sync(0xffffffffu, t, o));
        if (tid == 0) sred[0] = t;
    }
    __syncthreads();
    float r = sred[0];
    __syncthreads();
    return r;
}

__device__ __forceinline__ float blockSum(float v, float* sred) {
    #pragma unroll
    for (int o = 16; o; o >>= 1) v += __shfl_xor_sync(0xffffffffu, v, o);
    int tid = threadIdx.x;
    if ((tid & 31) == 0) sred[tid >> 5] = v;
    __syncthreads();
    if (tid < 32) {
        float t = (tid < 8) ? sred[tid] : 0.f;
        #pragma unroll
        for (int o = 4; o; o >>= 1) t += __shfl_xor_sync(0xffffffffu, t, o);
        if (tid == 0) sred[0] = t;
    }
    __syncthreads();
    float r = sred[0];
    __syncthreads();
    return r;
}

// ---------------- weight pack: W[l][k][0..639] = [wq | wkv] ----------------
__global__ __launch_bounds__(256) void pack_qkv(
    const float* __restrict__ wq, const float* __restrict__ wkv,
    float* __restrict__ W)
{
    long i4 = (long)blockIdx.x * 256 + threadIdx.x;
    long c4 = i4 % 160, rk = i4 / 160;
    float4 v;
    if (c4 < 128) v = *(const float4*)(wq + rk * 512 + c4 * 4);
    else          v = *(const float4*)(wkv + rk * 128 + (c4 - 128) * 4);
    *(float4*)(W + rk * 640 + c4 * 4) = v;
}

// ---------------- tf32 tensor-core GEMM, 4-stage cp.async pipeline ------------
// C = A @ B (+Res). 128x128x16 tiles. REQUIRES: M%128==0, N%128==0, K%16==0,
// K/16 >= 4. Dynamic smem: 4 stages x (128x20 + 16x136) floats = 75776 B.
#define STAGE_FLOATS (128 * 20 + 16 * 136)      // 4736
#define TGEMM_SMEM   (4 * STAGE_FLOATS * (int)sizeof(float))

template<int FUSE>
__global__ __launch_bounds__(256, 2) void tgemm_k(
    const float* __restrict__ A, int lda,
    const float* __restrict__ Bm, int ldb,
    float* __restrict__ C, int ldc,
    const float* __restrict__ Res, int ldr,
    int N, int K)
{
    extern __shared__ float smem_pool[];

    const int tid  = threadIdx.x;
    const int lane = tid & 31;
    const int warp = tid >> 5;
    const int wm = warp >> 2;
    const int wn = warp & 3;
    const int row0 = blockIdx.y << 7;
    const int col0 = blockIdx.x << 7;

    const int am = tid >> 2;           // 0..63 (+64)
    const int ak = (tid & 3) << 2;     // 0,4,8,12
    const int bk = tid >> 5;           // 0..7 (+8)
    const int bn = (tid & 31) << 2;    // 0..124

    const int gr = lane >> 2;
    const int gk = lane & 3;

    float acc[4][4][4];
    #pragma unroll
    for (int mi = 0; mi < 4; mi++)
        #pragma unroll
        for (int ni = 0; ni < 4; ni++)
            #pragma unroll
            for (int c = 0; c < 4; c++) acc[mi][ni][c] = 0.f;

    // per-thread source pointers
    const float* a0p = A + (long)(row0 + am) * lda + ak;
    const float* a1p = A + (long)(row0 + am + 64) * lda + ak;
    const float* b0p = Bm + (long)bk * ldb + col0 + bn;
    const float* b1p = Bm + (long)(bk + 8) * ldb + col0 + bn;

    // issue one stage's copies (4 x 16B per thread)
    auto issue = [&](int s, int k0) {
        float* base = smem_pool + s * STAGE_FLOATS;
        float (*As_)[20]  = (float(*)[20])base;
        float (*Bs_)[136] = (float(*)[136])(base + 128 * 20);
        cp16(&As_[am][ak],      a0p + k0);
        cp16(&As_[am + 64][ak], a1p + k0);
        cp16(&Bs_[bk][bn],      b0p + (long)k0 * ldb);
        cp16(&Bs_[bk + 8][bn],  b1p + (long)k0 * ldb);
    };

    const int niter = K >> 4;
    // prologue: stages 0..2
    #pragma unroll
    for (int s = 0; s < 3; s++) {
        issue(s, s * 16);
        CP_COMMIT();
    }

    for (int i = 0; i < niter; i++) {
        const int buf = i & 3;
        CP_WAIT2();                 // stage i resident
        __syncthreads();            // all compute(i-1) done; stage i visible to all
        if (i + 3 < niter) issue((i + 3) & 3, (i + 3) * 16);
        CP_COMMIT();                // keep group count uniform

        float* base = smem_pool + buf * STAGE_FLOATS;
        float (*Asb)[20]  = (float(*)[20])base;
        float (*Bsb)[136] = (float(*)[136])(base + 128 * 20);

        #pragma unroll
        for (int ks = 0; ks < 16; ks += 8) {
            unsigned a[4][4], b[4][2];
            #pragma unroll
            for (int mi = 0; mi < 4; mi++) {
                int r = wm * 64 + mi * 16 + gr;
                a[mi][0] = f2tfu(Asb[r    ][ks + gk]);
                a[mi][1] = f2tfu(Asb[r + 8][ks + gk]);
                a[mi][2] = f2tfu(Asb[r    ][ks + gk + 4]);
                a[mi][3] = f2tfu(Asb[r + 8][ks + gk + 4]);
            }
            #pragma unroll
            for (int ni = 0; ni < 4; ni++) {
                int c = wn * 32 + ni * 8 + gr;
                b[ni][0] = f2tfu(Bsb[ks + gk    ][c]);
                b[ni][1] = f2tfu(Bsb[ks + gk + 4][c]);
            }
            #pragma unroll
            for (int mi = 0; mi < 4; mi++)
                #pragma unroll
                for (int ni = 0; ni < 4; ni++)
                    mma_tf32(acc[mi][ni], a[mi], b[ni]);
        }
    }

    // ---- epilogue (N multiple of 128 at every call site) ----
    #pragma unroll
    for (int mi = 0; mi < 4; mi++) {
        #pragma unroll
        for (int ni = 0; ni < 4; ni++) {
            int r  = row0 + wm * 64 + mi * 16 + gr;
            int cc = col0 + wn * 32 + ni * 8 + gk * 2;
            float* c0p = C + (long)r * ldc + cc;
            float* c2p = C + (long)(r + 8) * ldc + cc;
            float v0 = acc[mi][ni][0], v1 = acc[mi][ni][1];
            float v2 = acc[mi][ni][2], v3 = acc[mi][ni][3];
            if (FUSE) {
                float2 q0 = *(const float2*)(Res + (long)r * ldr + cc);
                float2 q2 = *(const float2*)(Res + (long)(r + 8) * ldr + cc);
                v0 += q0.x; v1 += q0.y; v2 += q2.x; v3 += q2.y;
            }
            *(float2*)c0p = make_float2(v0, v1);
            *(float2*)c2p = make_float2(v2, v3);
        }
    }
}

// ---------------- small 64x64-tile tf32 GEMM ----------------
__global__ __launch_bounds__(128) void sgemm64_k(
    const float* __restrict__ A, int lda,
    const float* __restrict__ Bm, int ldb,
    float* __restrict__ C, int ldc, int K)
{
    __shared__ float As[64][20];
    __shared__ float Bs[16][72];
    const int tid = threadIdx.x;
    const int lane = tid & 31, warp = tid >> 5;
    const int wm = warp >> 1, wn = warp & 1;
    const int row0 = blockIdx.y << 6, col0 = blockIdx.x << 6;
    const int gr = lane >> 2, gk = lane & 3;

    const int am = tid >> 1, ak = (tid & 1) * 8;
    const int bkr = tid >> 3, bc = (tid & 7) * 8;

    float acc[2][4][4];
    #pragma unroll
    for (int mi = 0; mi < 2; mi++)
        #pragma unroll
        for (int ni = 0; ni < 4; ni++)
            #pragma unroll
            for (int e = 0; e < 4; e++) acc[mi][ni][e] = 0.f;

    for (int k0 = 0; k0 < K; k0 += 16) {
        float4 a0 = *(const float4*)(A + (long)(row0 + am) * lda + k0 + ak);
        float4 a1 = *(const float4*)(A + (long)(row0 + am) * lda + k0 + ak + 4);
        As[am][ak + 0] = f2tf(a0.x); As[am][ak + 1] = f2tf(a0.y);
        As[am][ak + 2] = f2tf(a0.z); As[am][ak + 3] = f2tf(a0.w);
        As[am][ak + 4] = f2tf(a1.x); As[am][ak + 5] = f2tf(a1.y);
        As[am][ak + 6] = f2tf(a1.z); As[am][ak + 7] = f2tf(a1.w);
        float4 b0 = *(const float4*)(Bm + (long)(k0 + bkr) * ldb + col0 + bc);
        float4 b1 = *(const float4*)(Bm + (long)(k0 + bkr) * ldb + col0 + bc + 4);
        Bs[bkr][bc + 0] = f2tf(b0.x); Bs[bkr][bc + 1] = f2tf(b0.y);
        Bs[bkr][bc + 2] = f2tf(b0.z); Bs[bkr][bc + 3] = f2tf(b0.w);
        Bs[bkr][bc + 4] = f2tf(b1.x); Bs[bkr][bc + 5] = f2tf(b1.y);
        Bs[bkr][bc + 6] = f2tf(b1.z); Bs[bkr][bc + 7] = f2tf(b1.w);
        __syncthreads();
        #pragma unroll
        for (int ks = 0; ks < 16; ks += 8) {
            unsigned a[2][4], b[4][2];
            #pragma unroll
            for (int mi = 0; mi < 2; mi++) {
                int r = wm * 32 + mi * 16 + gr;
                a[mi][0] = __float_as_uint(As[r    ][ks + gk]);
                a[mi][1] = __float_as_uint(As[r + 8][ks + gk]);
                a[mi][2] = __float_as_uint(As[r    ][ks + gk + 4]);
                a[mi][3] = __float_as_uint(As[r + 8][ks + gk + 4]);
            }
            #pragma unroll
            for (int ni = 0; ni < 4; ni++) {
                int c = wn * 32 + ni * 8 + gr;
                b[ni][0] = __float_as_uint(Bs[ks + gk    ][c]);
                b[ni][1] = __float_as_uint(Bs[ks + gk + 4][c]);
            }
            #pragma unroll
            for (int mi = 0; mi < 2; mi++)
                #pragma unroll
                for (int ni = 0; ni < 4; ni++)
                    mma_tf32(acc[mi][ni], a[mi], b[ni]);
        }
        __syncthreads();
    }

    #pragma unroll
    for (int mi = 0; mi < 2; mi++)
        #pragma unroll
        for (int ni = 0; ni < 4; ni++) {
            int r  = row0 + wm * 32 + mi * 16 + gr;
            int cc = col0 + wn * 32 + ni * 8 + gk * 2;
            *(float2*)(C + (long)r * ldc + cc)       = make_float2(acc[mi][ni][0], acc[mi][ni][1]);
            *(float2*)(C + (long)(r + 8) * ldc + cc) = make_float2(acc[mi][ni][2], acc[mi][ni][3]);
        }
}

// ---------------- fused flash attention ----------------
template<bool CAUSAL>
__global__ __launch_bounds__(128) void flash_attn(
    const float* __restrict__ Q, int ldq,
    const float* __restrict__ Kt,
    const float* __restrict__ V,
    float* __restrict__ O,
    const float* __restrict__ emb,
    int Ltot)
{
    extern __shared__ float sm[];
    float (*Qs)[68] = (float(*)[68])sm;
    float (*Ks)[68] = (float(*)[68])(sm + 64 * 68);
    float (*Vs)[68] = (float(*)[68])(sm + 2 * 64 * 68);
    float (*Ps)[68] = (float(*)[68])(sm + 3 * 64 * 68);
    float* biasLUT  = sm + 4 * 64 * 68;

    const int qi = blockIdx.x, h = blockIdx.y, b = blockIdx.z;
    const int q0 = qi << 6;
    const int tid = threadIdx.x;
    const int warp = tid >> 5, lane = tid & 31;
    const int gr = lane >> 2, gk = lane & 3;
    const int r0 = (warp << 4) + gr;

    if (CAUSAL) {
        for (int n = tid; n < 1024; n += 128) {
            int bucket;
            if (n < 16) bucket = n;
            else {
                int lg = (int)(logf((float)n * 0.0625f) * 7.69486038f);
                bucket = min(16 + lg, 31);
            }
            biasLUT[n] = emb[bucket * 8 + h];
        }
    }

    {
        const int row = tid >> 1, half = tid & 1;
        const float* srcp = Q + (long)(b * 1024 + q0 + row) * ldq + h * 64 + half * 32;
        float vals[32];
        #pragma unroll
        for (int e = 0; e < 8; e++)
            *(float4*)&vals[e * 4] = *(const float4*)(srcp + e * 4);
        if (CAUSAL && half == 0) {
            int t = q0 + row;
            #pragma unroll
            for (int i = 0; i < 16; i++) {
                float f = (float)t * powf(10000.0f, -(float)i * 0.0625f);
                float s, c; sincosf(f, &s, &c);
                float x1 = vals[i], x2 = vals[i + 16];
                vals[i]      = x1 * c - x2 * s;
                vals[i + 16] = x2 * c + x1 * s;
            }
        }
        #pragma unroll
        for (int i = 0; i < 32; i++)
            Qs[row][half * 32 + i] = f2tf(vals[i] * 0.125f);
    }

    float m0 = -1e30f, m1 = -1e30f, l0 = 0.f, l1 = 0.f;
    float co[8][4];
    #pragma unroll
    for (int nt = 0; nt < 8; nt++)
        #pragma unroll
        for (int e = 0; e < 4; e++) co[nt][e] = 0.f;

    const int ntiles = CAUSAL ? (qi + 2) : ((Ltot + 63) >> 6);

    for (int t = 0; t < ntiles; t++) {
        const int j0 = t << 6;
        __syncthreads();
        const float* ksrc = Kt + (long)b * 64 * LDS_ + j0;
        const float* vsrc = V + ((long)b * LDS_ + j0) * 64;
        if (j0 + 64 <= Ltot) {
            #pragma unroll
            for (int it = 0; it < 8; it++) {
                int idx = tid + it * 128;
                int r = idx >> 4, c4 = (idx & 15) << 2;
                float4 k4 = *(const float4*)(ksrc + (long)r * LDS_ + c4);
                Ks[r][c4 + 0] = f2tf(k4.x); Ks[r][c4 + 1] = f2tf(k4.y);
                Ks[r][c4 + 2] = f2tf(k4.z); Ks[r][c4 + 3] = f2tf(k4.w);
                float4 vv = *(const float4*)(vsrc + (long)r * 64 + c4);
                Vs[r][c4 + 0] = f2tf(vv.x); Vs[r][c4 + 1] = f2tf(vv.y);
                Vs[r][c4 + 2] = f2tf(vv.z); Vs[r][c4 + 3] = f2tf(vv.w);
            }
        } else {
            #pragma unroll
            for (int it = 0; it < 8; it++) {
                int idx = tid + it * 128;
                int r = idx >> 4, c4 = (idx & 15) << 2;
                #pragma unroll
                for (int e = 0; e < 4; e++) {
                    int jk = j0 + c4 + e;
                    Ks[r][c4 + e] = (jk < Ltot) ? f2tf(ksrc[(long)r * LDS_ + c4 + e]) : 0.f;
                }
                int jv = j0 + r;
                #pragma unroll
                for (int e = 0; e < 4; e++)
                    Vs[r][c4 + e] = (jv < Ltot) ? f2tf(vsrc[(long)r * 64 + c4 + e]) : 0.f;
            }
        }
        __syncthreads();

        float cs[8][4];
        #pragma unroll
        for (int nt = 0; nt < 8; nt++)
            #pragma unroll
            for (int e = 0; e < 4; e++) cs[nt][e] = 0.f;
        #pragma unroll
        for (int ks = 0; ks < 64; ks += 8) {
            unsigned a[4];
            a[0] = __float_as_uint(Qs[r0    ][ks + gk]);
            a[1] = __float_as_uint(Qs[r0 + 8][ks + gk]);
            a[2] = __float_as_uint(Qs[r0    ][ks + gk + 4]);
            a[3] = __float_as_uint(Qs[r0 + 8][ks + gk + 4]);
            #pragma unroll
            for (int nt = 0; nt < 8; nt++) {
                unsigned bb[2];
                bb[0] = __float_as_uint(Ks[ks + gk    ][nt * 8 + gr]);
                bb[1] = __float_as_uint(Ks[ks + gk + 4][nt * 8 + gr]);
                mma_tf32(cs[nt], a, bb);
            }
        }

        const int i0 = q0 + r0, i1 = i0 + 8;
        float tm0 = -1e30f, tm1 = -1e30f;
        #pragma unroll
        for (int nt = 0; nt < 8; nt++) {
            #pragma unroll
            for (int e = 0; e < 2; e++) {
                int jj = j0 + nt * 8 + gk * 2 + e;
                float s0 = cs[nt][e], s1 = cs[nt][2 + e];
                if (CAUSAL) {
                    s0 = (jj <= i0 + 1) ? s0 + biasLUT[max(i0 - jj, 0)] : -1e30f;
                    s1 = (jj <= i1 + 1) ? s1 + biasLUT[max(i1 - jj, 0)] : -1e30f;
                } else {
                    if (jj >= Ltot) { s0 = -1e30f; s1 = -1e30f; }
                }
                cs[nt][e] = s0; cs[nt][2 + e] = s1;
                tm0 = fmaxf(tm0, s0); tm1 = fmaxf(tm1, s1);
            }
        }
        tm0 = fmaxf(tm0, __shfl_xor_sync(0xffffffffu, tm0, 1));
        tm0 = fmaxf(tm0, __shfl_xor_sync(0xffffffffu, tm0, 2));
        tm1 = fmaxf(tm1, __shfl_xor_sync(0xffffffffu, tm1, 1));
        tm1 = fmaxf(tm1, __shfl_xor_sync(0xffffffffu, tm1, 2));

        float mn0 = fmaxf(m0, tm0), mn1 = fmaxf(m1, tm1);
        float sc0 = __expf(m0 - mn0), sc1 = __expf(m1 - mn1);
        float ps0 = 0.f, ps1 = 0.f;
        #pragma unroll
        for (int nt = 0; nt < 8; nt++) {
            float p00 = __expf(cs[nt][0] - mn0);
            float p01 = __expf(cs[nt][1] - mn0);
            float p10 = __expf(cs[nt][2] - mn1);
            float p11 = __expf(cs[nt][3] - mn1);
            ps0 += p00 + p01; ps1 += p10 + p11;
            int c = nt * 8 + gk * 2;
            *(float2*)&Ps[r0    ][c] = make_float2(f2tf(p00), f2tf(p01));
            *(float2*)&Ps[r0 + 8][c] = make_float2(f2tf(p10), f2tf(p11));
            co[nt][0] *= sc0; co[nt][1] *= sc0;
            co[nt][2] *= sc1; co[nt][3] *= sc1;
        }
        ps0 += __shfl_xor_sync(0xffffffffu, ps0, 1);
        ps0 += __shfl_xor_sync(0xffffffffu, ps0, 2);
        ps1 += __shfl_xor_sync(0xffffffffu, ps1, 1);
        ps1 += __shfl_xor_sync(0xffffffffu, ps1, 2);
        l0 = l0 * sc0 + ps0; l1 = l1 * sc1 + ps1;
        m0 = mn0; m1 = mn1;
        __syncthreads();

        #pragma unroll
        for (int ks = 0; ks < 64; ks += 8) {
            unsigned a[4];
            a[0] = __float_as_uint(Ps[r0    ][ks + gk]);
            a[1] = __float_as_uint(Ps[r0 + 8][ks + gk]);
            a[2] = __float_as_uint(Ps[r0    ][ks + gk + 4]);
            a[3] = __float_as_uint(Ps[r0 + 8][ks + gk + 4]);
            #pragma unroll
            for (int nt = 0; nt < 8; nt++) {
                unsigned bb[2];
                bb[0] = __float_as_uint(Vs[ks + gk    ][nt * 8 + gr]);
                bb[1] = __float_as_uint(Vs[ks + gk + 4][nt * 8 + gr]);
                mma_tf32(co[nt], a, bb);
            }
        }
    }

    const float inv0 = 1.f / l0, inv1 = 1.f / l1;
    float* o0 = O + (long)(b * 1024 + q0 + r0) * 512 + h * 64;
    float* o1 = o0 + 8 * 512;
    #pragma unroll
    for (int nt = 0; nt < 8; nt++) {
        int c = nt * 8 + gk * 2;
        *(float2*)(o0 + c) = make_float2(co[nt][0] * inv0, co[nt][1] * inv0);
        *(float2*)(o1 + c) = make_float2(co[nt][2] * inv1, co[nt][3] * inv1);
    }
}

// ---------------- LayerNorm: 0=plain, 2=stable ----------------
template<int MODE>
__global__ __launch_bounds__(256) void ln_kernel(
    const float* __restrict__ in, const float* __restrict__ gam,
    float* __restrict__ out, int C)
{
    __shared__ float sred[8];
    long row = blockIdx.x;
    const float* x = in + row * (long)C;
    int tid = threadIdx.x;
    bool two = (C > 256);
    float v0 = x[tid];
    float v1 = two ? x[tid + 256] : 0.f;

    if (MODE == 2) {
        float mx = two ? fmaxf(v0, v1) : v0;
        mx = blockMax(mx, sred);
        float inv = 1.0f / mx;
        v0 *= inv; v1 *= inv;
    }
    float s = blockSum(v0 + v1, sred);
    float mu = s / (float)C;
    float d0 = v0 - mu, d1 = v1 - mu;
    float sq = d0 * d0 + (two ? d1 * d1 : 0.f);
    sq = blockSum(sq, sred);
    float rstd = rsqrtf(sq / (float)C + 1e-5f);

    out[row * (long)C + tid] = d0 * rstd * gam[tid];
    if (two) out[row * (long)C + tid + 256] = d1 * rstd * gam[tid + 256];
}

// ---- fused: X = X + LN(T)*g1 ; XN = LN(X)*g2   (C = 512) ----
__global__ __launch_bounds__(256) void ln_res_ln(
    const float* __restrict__ T, const float* __restrict__ g1,
    const float* __restrict__ g2,
    float* __restrict__ X, float* __restrict__ XN)
{
    __shared__ float sred[8];
    long row = blockIdx.x;
    int tid = threadIdx.x;
    const float* t = T + row * 512;
    float v0 = t[tid], v1 = t[tid + 256];

    float s = blockSum(v0 + v1, sred);
    float mu = s * (1.0f / 512.0f);
    float d0 = v0 - mu, d1 = v1 - mu;
    float sq = blockSum(d0 * d0 + d1 * d1, sred);
    float rstd = rsqrtf(sq * (1.0f / 512.0f) + 1e-5f);

    float x0 = d0 * rstd * g1[tid]       + X[row * 512 + tid];
    float x1 = d1 * rstd * g1[tid + 256] + X[row * 512 + tid + 256];
    X[row * 512 + tid]       = x0;
    X[row * 512 + tid + 256] = x1;

    float s2 = blockSum(x0 + x1, sred);
    float mu2 = s2 * (1.0f / 512.0f);
    float e0 = x0 - mu2, e1 = x1 - mu2;
    float sq2 = blockSum(e0 * e0 + e1 * e1, sred);
    float rstd2 = rsqrtf(sq2 * (1.0f / 512.0f) + 1e-5f);

    XN[row * 512 + tid]       = e0 * rstd2 * g2[tid];
    XN[row * 512 + tid + 256] = e1 * rstd2 * g2[tid + 256];
}

// ---------------- KV prepare ----------------
template<bool ROT>
__global__ void prep_kv(const float* __restrict__ src, int ld, int koff,
                        const float* __restrict__ nullkv,
                        float* __restrict__ Kt, float* __restrict__ V, int srcN)
{
    int t = blockIdx.x;
    int b = blockIdx.y;
    int d = threadIdx.x;
    const float* kv = src + ((long)b * srcN + t) * ld + koff;
    float k = kv[d], v = kv[64 + d];
    V[((long)b * LDS_ + (t + 1)) * 64 + d] = v;
    float kr = k;
    if (ROT && d < 32) {
        int i = d & 15;
        float f = (float)t * powf(10000.0f, -(float)i * 0.0625f);
        float s, c; sincosf(f, &s, &c);
        float p = kv[(d < 16) ? d + 16 : d - 16];
        kr = (d < 16) ? (k * c - p * s) : (k * c + p * s);
    }
    Kt[((long)b * 64 + d) * LDS_ + (t + 1)] = kr;
    if (t == 0) {
        V[((long)b * LDS_) * 64 + d] = nullkv[64 + d];
        Kt[((long)b * 64 + d) * LDS_] = nullkv[d];
    }
    if (t < 15) {
        V[((long)b * LDS_ + srcN + 1 + t) * 64 + d] = 0.f;
    }
}

// ---------------- FFN gate ----------------
__global__ __launch_bounds__(256) void silu_gate(const float* __restrict__ H1,
                                                 float* __restrict__ G)
{
    long idx = (long)blockIdx.x * 256 + threadIdx.x;
    long r = idx >> 11, c = idx & 2047;
    float hh = H1[r * 4096 + c];
    float gt = H1[r * 4096 + 2048 + c];
    G[idx] = hh * gt / (1.0f + expf(-gt));
}

// ---------------- host helpers ----------------
static inline void gemm(const float* A, int lda,
                        const float* Bm, int ldb,
                        float* C, int ldc,
                        int M, int N, int K,
                        const float* Res = nullptr, int ldr = 0)
{
    dim3 g(N / 128, M / 128, 1);
    if (Res) tgemm_k<1><<<g, 256, TGEMM_SMEM>>>(A, lda, Bm, ldb, C, ldc, Res, ldr, N, K);
    else     tgemm_k<0><<<g, 256, TGEMM_SMEM>>>(A, lda, Bm, ldb, C, ldc, nullptr, 0, N, K);
}

#define FLASH_SMEM ((4 * 64 * 68 + 1024) * (int)sizeof(float))

extern "C" void kernel_launch(void* const* d_in, const int* in_sizes, int n_in,
                              void* d_out, int out_size)
{
    const float* x         = (const float*)d_in[0];
    const float* ctx       = (const float*)d_in[1];
    const float* rel_emb   = (const float*)d_in[2];
    const float* sa_norm_g = (const float*)d_in[3];
    const float* sa_wq     = (const float*)d_in[4];
    const float* sa_wkv    = (const float*)d_in[5];
    const float* sa_nkv    = (const float*)d_in[6];
    const float* sa_wo     = (const float*)d_in[7];
    const float* sa_out_g  = (const float*)d_in[8];
    const float* ca_norm_g = (const float*)d_in[9];
    const float* ca_ctx_g  = (const float*)d_in[10];
    const float* ca_wq     = (const float*)d_in[11];
    const float* ca_wkv    = (const float*)d_in[12];
    const float* ca_nkv    = (const float*)d_in[13];
    const float* ca_wo     = (const float*)d_in[14];
    const float* ca_out_g  = (const float*)d_in[15];
    const float* ff_norm_g = (const float*)d_in[16];
    const float* ff_w1     = (const float*)d_in[17];
    const float* ff_w2     = (const float*)d_in[18];
    const float* norm_g    = (const float*)d_in[19];

    float *pX, *pXN, *pQ, *pQKV, *pKVp, *pKt, *pV, *pO, *pT, *pH1, *pG, *pCTXN, *pW;
    cudaGetSymbolAddress((void**)&pX,    g_X);
    cudaGetSymbolAddress((void**)&pXN,   g_XN);
    cudaGetSymbolAddress((void**)&pQ,    g_Q);
    cudaGetSymbolAddress((void**)&pQKV,  g_QKV);
    cudaGetSymbolAddress((void**)&pKVp,  g_KVp);
    cudaGetSymbolAddress((void**)&pKt,   g_Kt);
    cudaGetSymbolAddress((void**)&pV,    g_V);
    cudaGetSymbolAddress((void**)&pO,    g_O);
    cudaGetSymbolAddress((void**)&pT,    g_T);
    cudaGetSymbolAddress((void**)&pH1,   g_H1);
    cudaGetSymbolAddress((void**)&pG,    g_G);
    cudaGetSymbolAddress((void**)&pCTXN, g_CTXN);
    cudaGetSymbolAddress((void**)&pW,    g_Wqkv);

    cudaFuncSetAttribute(flash_attn<true>,
                         cudaFuncAttributeMaxDynamicSharedMemorySize, FLASH_SMEM);
    cudaFuncSetAttribute(flash_attn<false>,
                         cudaFuncAttributeMaxDynamicSharedMemorySize, FLASH_SMEM);
    cudaFuncSetAttribute(tgemm_k<0>,
                         cudaFuncAttributeMaxDynamicSharedMemorySize, TGEMM_SMEM);
    cudaFuncSetAttribute(tgemm_k<1>,
                         cudaFuncAttributeMaxDynamicSharedMemorySize, TGEMM_SMEM);

    cudaMemcpyAsync(pX, x, (size_t)Bsz * Nq * Dm * sizeof(float),
                    cudaMemcpyDeviceToDevice);
    pack_qkv<<<1920, 256>>>(sa_wq, sa_wkv, pW);

    for (int l = 0; l < Ll; l++) {
        // ===== self attention =====
        ln_kernel<0><<<4096, 256>>>(pX, sa_norm_g + l * 512, pXN, 512);
        gemm(pXN, 512, pW + (long)l * 512 * 640, 640, pQKV, 640, 4096, 640, 512);
        prep_kv<true><<<dim3(1024, 4), 64>>>(pQKV, 640, 512,
                                             sa_nkv + l * 128, pKt, pV, 1024);
        flash_attn<true><<<dim3(16, 8, 4), 128, FLASH_SMEM>>>(
            pQKV, 640, pKt, pV, pO, rel_emb, 1025);
        gemm(pO, 512, sa_wo + (long)l * 512 * 512, 512, pT, 512, 4096, 512, 512);
        ln_res_ln<<<4096, 256>>>(pT, sa_out_g + l * 512, ca_norm_g + l * 512, pX, pXN);

        // ===== cross attention =====
        ln_kernel<0><<<2048, 256>>>(ctx, ca_ctx_g + l * 256, pCTXN, 256);
        gemm(pXN, 512, ca_wq + (long)l * 512 * 512, 512, pQ, 512, 4096, 512, 512);
        sgemm64_k<<<dim3(2, 32), 128>>>(pCTXN, 256,
                                        ca_wkv + (long)l * 256 * 128, 128,
                                        pKVp, 128, 256);
        prep_kv<false><<<dim3(512, 4), 64>>>(pKVp, 128, 0,
                                             ca_nkv + l * 128, pKt, pV, 512);
        flash_attn<false><<<dim3(16, 8, 4), 128, FLASH_SMEM>>>(
            pQ, 512, pKt, pV, pO, nullptr, 513);
        gemm(pO, 512, ca_wo + (long)l * 512 * 512, 512, pT, 512, 4096, 512, 512);
        ln_res_ln<<<4096, 256>>>(pT, ca_out_g + l * 512, ff_norm_g + l * 512, pX, pXN);

        // ===== feed forward =====
        gemm(pXN, 512, ff_w1 + (long)l * 512 * 4096, 4096, pH1, 4096, 4096, 4096, 512);
        silu_gate<<<32768, 256>>>(pH1, pG);
        gemm(pG, 2048, ff_w2 + (long)l * 2048 * 512, 512, pX, 512, 4096, 512, 2048, pX, 512);
    }

    ln_kernel<2><<<4096, 256>>>(pX, norm_g, (float*)d_out, 512);
}

// round 14
// speedup vs baseline: 1.1710x; 1.0077x over previous
#include <cuda_runtime.h>
#include <math.h>

// ---------------- problem dims ----------------
#define Bsz 4
#define Nq  1024
#define Mctx 512
#define Dm  512
#define Pm  256
#define Hh  8
#define DHh 64
#define Ll  6
#define FIi 2048
#define LDS_ 1040

// ---------------- device scratch ----------------
__device__ float g_X   [(long)Bsz*Nq*Dm];
__device__ float g_XN  [(long)Bsz*Nq*Dm];
__device__ float g_Q   [(long)Bsz*Nq*Dm];
__device__ float g_QKV [(long)Bsz*Nq*640];
__device__ float g_O   [(long)Bsz*Nq*Dm];
__device__ float g_T   [(long)Bsz*Nq*Dm];
__device__ float g_KVp [(long)Bsz*Nq*128];
__device__ float g_Kt  [(long)Bsz*64*LDS_];
__device__ float g_V   [(long)Bsz*LDS_*64];
__device__ float g_H1  [(long)Bsz*Nq*2*FIi];
__device__ float g_G   [(long)Bsz*Nq*FIi];
__device__ float g_CTXN[(long)Bsz*Mctx*Pm];
// pre-rounded (tf32) weights
__device__ float g_Wqkv [(long)Ll*Dm*640];
__device__ float g_Wsawo[(long)Ll*Dm*Dm];
__device__ float g_Wcawq[(long)Ll*Dm*Dm];
__device__ float g_Wcawo[(long)Ll*Dm*Dm];
__device__ float g_Wff1 [(long)Ll*Dm*2*FIi];
__device__ float g_Wff2 [(long)Ll*FIi*Dm];

// ---------------- helpers ----------------
__device__ __forceinline__ float f2tf(float f) {
    unsigned u;
    asm("cvt.rna.tf32.f32 %0, %1;" : "=r"(u) : "f"(f));
    return __uint_as_float(u);
}

__device__ __forceinline__ void mma_tf32(float* d, const unsigned* a, const unsigned* b) {
    asm volatile(
        "mma.sync.aligned.m16n8k8.row.col.f32.tf32.tf32.f32 "
        "{%0,%1,%2,%3}, {%4,%5,%6,%7}, {%8,%9}, {%0,%1,%2,%3};"
        : "+f"(d[0]), "+f"(d[1]), "+f"(d[2]), "+f"(d[3])
        : "r"(a[0]), "r"(a[1]), "r"(a[2]), "r"(a[3]), "r"(b[0]), "r"(b[1]));
}

__device__ __forceinline__ void cp16(void* smem_dst, const void* gsrc) {
    unsigned s = (unsigned)__cvta_generic_to_shared(smem_dst);
    asm volatile("cp.async.ca.shared.global [%0], [%1], 16;" :: "r"(s), "l"(gsrc));
}
#define CP_COMMIT()  asm volatile("cp.async.commit_group;")
#define CP_WAIT2()   asm volatile("cp.async.wait_group 2;")

__device__ __forceinline__ float blockMax(float v, float* sred) {
    #pragma unroll
    for (int o = 16; o; o >>= 1) v = fmaxf(v, __shfl_xor_sync(0xffffffffu, v, o));
    int tid = threadIdx.x;
    if ((tid & 31) == 0) sred[tid >> 5] = v;
    __syncthreads();
    if (tid < 32) {
        float t = (tid < 8) ? sred[tid] : -3.4e38f;
        #pragma unroll
        for (int o = 4; o; o >>= 1) t = fmaxf(t, __shfl_xor_sync(0xffffffffu, t, o));
        if (tid == 0) sred[0] = t;
    }
    __syncthreads();
    float r = sred[0];
    __syncthreads();
    return r;
}

__device__ __forceinline__ float blockSum(float v, float* sred) {
    #pragma unroll
    for (int o = 16; o; o >>= 1) v += __shfl_xor_sync(0xffffffffu, v, o);
    int tid = threadIdx.x;
    if ((tid & 31) == 0) sred[tid >> 5] = v;
    __syncthreads();
    if (tid < 32) {
        float t = (tid < 8) ? sred[tid] : 0.f;
        #pragma unroll
        for (int o = 4; o; o >>= 1) t += __shfl_xor_sync(0xffffffffu, t, o);
        if (tid == 0) sred[0] = t;
    }
    __syncthreads();
    float r = sred[0];
    __syncthreads();
    return r;
}

// ---------------- rounding copy (tf32) ----------------
__global__ __launch_bounds__(256) void round_tf32(
    const float* __restrict__ src, float* __restrict__ dst)
{
    long i = ((long)blockIdx.x * 256 + threadIdx.x) * 4;
    float4 v = *(const float4*)(src + i);
    v.x = f2tf(v.x); v.y = f2tf(v.y); v.z = f2tf(v.z); v.w = f2tf(v.w);
    *(float4*)(dst + i) = v;
}

// ---------------- weight pack (rounded): W[l][k][0..639] = [wq | wkv] ---------
__global__ __launch_bounds__(256) void pack_qkv(
    const float* __restrict__ wq, const float* __restrict__ wkv,
    float* __restrict__ W)
{
    long i4 = (long)blockIdx.x * 256 + threadIdx.x;
    long c4 = i4 % 160, rk = i4 / 160;
    float4 v;
    if (c4 < 128) v = *(const float4*)(wq + rk * 512 + c4 * 4);
    else          v = *(const float4*)(wkv + rk * 128 + (c4 - 128) * 4);
    v.x = f2tf(v.x); v.y = f2tf(v.y); v.z = f2tf(v.z); v.w = f2tf(v.w);
    *(float4*)(W + rk * 640 + c4 * 4) = v;
}

// ---------------- tf32 GEMM, 4-stage cp.async pipeline, pre-rounded inputs ----
// C = A @ B (+Res). REQUIRES: M%128==0, N%128==0, K%16==0, K/16>=4.
// A and B must already be tf32-rounded.
#define STAGE_FLOATS (128 * 20 + 16 * 136)      // 4736
#define TGEMM_SMEM   (4 * STAGE_FLOATS * (int)sizeof(float))

template<int FUSE>
__global__ __launch_bounds__(256, 2) void tgemm_k(
    const float* __restrict__ A, int lda,
    const float* __restrict__ Bm, int ldb,
    float* __restrict__ C, int ldc,
    const float* __restrict__ Res, int ldr,
    int N, int K)
{
    extern __shared__ float smem_pool[];

    const int tid  = threadIdx.x;
    const int lane = tid & 31;
    const int warp = tid >> 5;
    const int wm = warp >> 2;
    const int wn = warp & 3;
    const int row0 = blockIdx.y << 7;
    const int col0 = blockIdx.x << 7;

    const int am = tid >> 2;
    const int ak = (tid & 3) << 2;
    const int bk = tid >> 5;
    const int bn = (tid & 31) << 2;

    const int gr = lane >> 2;
    const int gk = lane & 3;

    float acc[4][4][4];
    #pragma unroll
    for (int mi = 0; mi < 4; mi++)
        #pragma unroll
        for (int ni = 0; ni < 4; ni++)
            #pragma unroll
            for (int c = 0; c < 4; c++) acc[mi][ni][c] = 0.f;

    const float* a0p = A + (long)(row0 + am) * lda + ak;
    const float* a1p = A + (long)(row0 + am + 64) * lda + ak;
    const float* b0p = Bm + (long)bk * ldb + col0 + bn;
    const float* b1p = Bm + (long)(bk + 8) * ldb + col0 + bn;

    auto issue = [&](int s, int k0) {
        float* base = smem_pool + s * STAGE_FLOATS;
        float (*As_)[20]  = (float(*)[20])base;
        float (*Bs_)[136] = (float(*)[136])(base + 128 * 20);
        cp16(&As_[am][ak],      a0p + k0);
        cp16(&As_[am + 64][ak], a1p + k0);
        cp16(&Bs_[bk][bn],      b0p + (long)k0 * ldb);
        cp16(&Bs_[bk + 8][bn],  b1p + (long)k0 * ldb);
    };

    const int niter = K >> 4;
    #pragma unroll
    for (int s = 0; s < 3; s++) {
        issue(s, s * 16);
        CP_COMMIT();
    }

    for (int i = 0; i < niter; i++) {
        const int buf = i & 3;
        CP_WAIT2();
        __syncthreads();
        if (i + 3 < niter) issue((i + 3) & 3, (i + 3) * 16);
        CP_COMMIT();

        float* base = smem_pool + buf * STAGE_FLOATS;
        float (*Asb)[20]  = (float(*)[20])base;
        float (*Bsb)[136] = (float(*)[136])(base + 128 * 20);

        #pragma unroll
        for (int ks = 0; ks < 16; ks += 8) {
            unsigned a[4][4], b[4][2];
            #pragma unroll
            for (int mi = 0; mi < 4; mi++) {
                int r = wm * 64 + mi * 16 + gr;
                a[mi][0] = __float_as_uint(Asb[r    ][ks + gk]);
                a[mi][1] = __float_as_uint(Asb[r + 8][ks + gk]);
                a[mi][2] = __float_as_uint(Asb[r    ][ks + gk + 4]);
                a[mi][3] = __float_as_uint(Asb[r + 8][ks + gk + 4]);
            }
            #pragma unroll
            for (int ni = 0; ni < 4; ni++) {
                int c = wn * 32 + ni * 8 + gr;
                b[ni][0] = __float_as_uint(Bsb[ks + gk    ][c]);
                b[ni][1] = __float_as_uint(Bsb[ks + gk + 4][c]);
            }
            #pragma unroll
            for (int mi = 0; mi < 4; mi++)
                #pragma unroll
                for (int ni = 0; ni < 4; ni++)
                    mma_tf32(acc[mi][ni], a[mi], b[ni]);
        }
    }

    #pragma unroll
    for (int mi = 0; mi < 4; mi++) {
        #pragma unroll
        for (int ni = 0; ni < 4; ni++) {
            int r  = row0 + wm * 64 + mi * 16 + gr;
            int cc = col0 + wn * 32 + ni * 8 + gk * 2;
            float* c0p = C + (long)r * ldc + cc;
            float* c2p = C + (long)(r + 8) * ldc + cc;
            float v0 = acc[mi][ni][0], v1 = acc[mi][ni][1];
            float v2 = acc[mi][ni][2], v3 = acc[mi][ni][3];
            if (FUSE) {
                float2 q0 = *(const float2*)(Res + (long)r * ldr + cc);
                float2 q2 = *(const float2*)(Res + (long)(r + 8) * ldr + cc);
                v0 += q0.x; v1 += q0.y; v2 += q2.x; v3 += q2.y;
            }
            *(float2*)c0p = make_float2(v0, v1);
            *(float2*)c2p = make_float2(v2, v3);
        }
    }
}

// ---------------- small 64x64-tile tf32 GEMM ----------------
__global__ __launch_bounds__(128) void sgemm64_k(
    const float* __restrict__ A, int lda,
    const float* __restrict__ Bm, int ldb,
    float* __restrict__ C, int ldc, int K)
{
    __shared__ float As[64][20];
    __shared__ float Bs[16][72];
    const int tid = threadIdx.x;
    const int lane = tid & 31, warp = tid >> 5;
    const int wm = warp >> 1, wn = warp & 1;
    const int row0 = blockIdx.y << 6, col0 = blockIdx.x << 6;
    const int gr = lane >> 2, gk = lane & 3;

    const int am = tid >> 1, ak = (tid & 1) * 8;
    const int bkr = tid >> 3, bc = (tid & 7) * 8;

    float acc[2][4][4];
    #pragma unroll
    for (int mi = 0; mi < 2; mi++)
        #pragma unroll
        for (int ni = 0; ni < 4; ni++)
            #pragma unroll
            for (int e = 0; e < 4; e++) acc[mi][ni][e] = 0.f;

    for (int k0 = 0; k0 < K; k0 += 16) {
        float4 a0 = *(const float4*)(A + (long)(row0 + am) * lda + k0 + ak);
        float4 a1 = *(const float4*)(A + (long)(row0 + am) * lda + k0 + ak + 4);
        As[am][ak + 0] = f2tf(a0.x); As[am][ak + 1] = f2tf(a0.y);
        As[am][ak + 2] = f2tf(a0.z); As[am][ak + 3] = f2tf(a0.w);
        As[am][ak + 4] = f2tf(a1.x); As[am][ak + 5] = f2tf(a1.y);
        As[am][ak + 6] = f2tf(a1.z); As[am][ak + 7] = f2tf(a1.w);
        float4 b0 = *(const float4*)(Bm + (long)(k0 + bkr) * ldb + col0 + bc);
        float4 b1 = *(const float4*)(Bm + (long)(k0 + bkr) * ldb + col0 + bc + 4);
        Bs[bkr][bc + 0] = f2tf(b0.x); Bs[bkr][bc + 1] = f2tf(b0.y);
        Bs[bkr][bc + 2] = f2tf(b0.z); Bs[bkr][bc + 3] = f2tf(b0.w);
        Bs[bkr][bc + 4] = f2tf(b1.x); Bs[bkr][bc + 5] = f2tf(b1.y);
        Bs[bkr][bc + 6] = f2tf(b1.z); Bs[bkr][bc + 7] = f2tf(b1.w);
        __syncthreads();
        #pragma unroll
        for (int ks = 0; ks < 16; ks += 8) {
            unsigned a[2][4], b[4][2];
            #pragma unroll
            for (int mi = 0; mi < 2; mi++) {
                int r = wm * 32 + mi * 16 + gr;
                a[mi][0] = __float_as_uint(As[r    ][ks + gk]);
                a[mi][1] = __float_as_uint(As[r + 8][ks + gk]);
                a[mi][2] = __float_as_uint(As[r    ][ks + gk + 4]);
                a[mi][3] = __float_as_uint(As[r + 8][ks + gk + 4]);
            }
            #pragma unroll
            for (int ni = 0; ni < 4; ni++) {
                int c = wn * 32 + ni * 8 + gr;
                b[ni][0] = __float_as_uint(Bs[ks + gk    ][c]);
                b[ni][1] = __float_as_uint(Bs[ks + gk + 4][c]);
            }
            #pragma unroll
            for (int mi = 0; mi < 2; mi++)
                #pragma unroll
                for (int ni = 0; ni < 4; ni++)
                    mma_tf32(acc[mi][ni], a[mi], b[ni]);
        }
        __syncthreads();
    }

    #pragma unroll
    for (int mi = 0; mi < 2; mi++)
        #pragma unroll
        for (int ni = 0; ni < 4; ni++) {
            int r  = row0 + wm * 32 + mi * 16 + gr;
            int cc = col0 + wn * 32 + ni * 8 + gk * 2;
            *(float2*)(C + (long)r * ldc + cc)       = make_float2(acc[mi][ni][0], acc[mi][ni][1]);
            *(float2*)(C + (long)(r + 8) * ldc + cc) = make_float2(acc[mi][ni][2], acc[mi][ni][3]);
        }
}

// ---------------- fused flash attention (O written tf32-rounded) --------------
template<bool CAUSAL>
__global__ __launch_bounds__(128) void flash_attn(
    const float* __restrict__ Q, int ldq,
    const float* __restrict__ Kt,
    const float* __restrict__ V,
    float* __restrict__ O,
    const float* __restrict__ emb,
    int Ltot)
{
    extern __shared__ float sm[];
    float (*Qs)[68] = (float(*)[68])sm;
    float (*Ks)[68] = (float(*)[68])(sm + 64 * 68);
    float (*Vs)[68] = (float(*)[68])(sm + 2 * 64 * 68);
    float (*Ps)[68] = (float(*)[68])(sm + 3 * 64 * 68);
    float* biasLUT  = sm + 4 * 64 * 68;

    const int qi = blockIdx.x, h = blockIdx.y, b = blockIdx.z;
    const int q0 = qi << 6;
    const int tid = threadIdx.x;
    const int warp = tid >> 5, lane = tid & 31;
    const int gr = lane >> 2, gk = lane & 3;
    const int r0 = (warp << 4) + gr;

    if (CAUSAL) {
        for (int n = tid; n < 1024; n += 128) {
            int bucket;
            if (n < 16) bucket = n;
            else {
                int lg = (int)(logf((float)n * 0.0625f) * 7.69486038f);
                bucket = min(16 + lg, 31);
            }
            biasLUT[n] = emb[bucket * 8 + h];
        }
    }

    {
        const int row = tid >> 1, half = tid & 1;
        const float* srcp = Q + (long)(b * 1024 + q0 + row) * ldq + h * 64 + half * 32;
        float vals[32];
        #pragma unroll
        for (int e = 0; e < 8; e++)
            *(float4*)&vals[e * 4] = *(const float4*)(srcp + e * 4);
        if (CAUSAL && half == 0) {
            int t = q0 + row;
            #pragma unroll
            for (int i = 0; i < 16; i++) {
                float f = (float)t * powf(10000.0f, -(float)i * 0.0625f);
                float s, c; sincosf(f, &s, &c);
                float x1 = vals[i], x2 = vals[i + 16];
                vals[i]      = x1 * c - x2 * s;
                vals[i + 16] = x2 * c + x1 * s;
            }
        }
        #pragma unroll
        for (int i = 0; i < 32; i++)
            Qs[row][half * 32 + i] = f2tf(vals[i] * 0.125f);
    }

    float m0 = -1e30f, m1 = -1e30f, l0 = 0.f, l1 = 0.f;
    float co[8][4];
    #pragma unroll
    for (int nt = 0; nt < 8; nt++)
        #pragma unroll
        for (int e = 0; e < 4; e++) co[nt][e] = 0.f;

    const int ntiles = CAUSAL ? (qi + 2) : ((Ltot + 63) >> 6);

    for (int t = 0; t < ntiles; t++) {
        const int j0 = t << 6;
        __syncthreads();
        const float* ksrc = Kt + (long)b * 64 * LDS_ + j0;
        const float* vsrc = V + ((long)b * LDS_ + j0) * 64;
        if (j0 + 64 <= Ltot) {
            #pragma unroll
            for (int it = 0; it < 8; it++) {
                int idx = tid + it * 128;
                int r = idx >> 4, c4 = (idx & 15) << 2;
                float4 k4 = *(const float4*)(ksrc + (long)r * LDS_ + c4);
                Ks[r][c4 + 0] = f2tf(k4.x); Ks[r][c4 + 1] = f2tf(k4.y);
                Ks[r][c4 + 2] = f2tf(k4.z); Ks[r][c4 + 3] = f2tf(k4.w);
                float4 vv = *(const float4*)(vsrc + (long)r * 64 + c4);
                Vs[r][c4 + 0] = f2tf(vv.x); Vs[r][c4 + 1] = f2tf(vv.y);
                Vs[r][c4 + 2] = f2tf(vv.z); Vs[r][c4 + 3] = f2tf(vv.w);
            }
        } else {
            #pragma unroll
            for (int it = 0; it < 8; it++) {
                int idx = tid + it * 128;
                int r = idx >> 4, c4 = (idx & 15) << 2;
                #pragma unroll
                for (int e = 0; e < 4; e++) {
                    int jk = j0 + c4 + e;
                    Ks[r][c4 + e] = (jk < Ltot) ? f2tf(ksrc[(long)r * LDS_ + c4 + e]) : 0.f;
                }
                int jv = j0 + r;
                #pragma unroll
                for (int e = 0; e < 4; e++)
                    Vs[r][c4 + e] = (jv < Ltot) ? f2tf(vsrc[(long)r * 64 + c4 + e]) : 0.f;
            }
        }
        __syncthreads();

        float cs[8][4];
        #pragma unroll
        for (int nt = 0; nt < 8; nt++)
            #pragma unroll
            for (int e = 0; e < 4; e++) cs[nt][e] = 0.f;
        #pragma unroll
        for (int ks = 0; ks < 64; ks += 8) {
            unsigned a[4];
            a[0] = __float_as_uint(Qs[r0    ][ks + gk]);
            a[1] = __float_as_uint(Qs[r0 + 8][ks + gk]);
            a[2] = __float_as_uint(Qs[r0    ][ks + gk + 4]);
            a[3] = __float_as_uint(Qs[r0 + 8][ks + gk + 4]);
            #pragma unroll
            for (int nt = 0; nt < 8; nt++) {
                unsigned bb[2];
                bb[0] = __float_as_uint(Ks[ks + gk    ][nt * 8 + gr]);
                bb[1] = __float_as_uint(Ks[ks + gk + 4][nt * 8 + gr]);
                mma_tf32(cs[nt], a, bb);
            }
        }

        const int i0 = q0 + r0, i1 = i0 + 8;
        float tm0 = -1e30f, tm1 = -1e30f;
        #pragma unroll
        for (int nt = 0; nt < 8; nt++) {
            #pragma unroll
            for (int e = 0; e < 2; e++) {
                int jj = j0 + nt * 8 + gk * 2 + e;
                float s0 = cs[nt][e], s1 = cs[nt][2 + e];
                if (CAUSAL) {
                    s0 = (jj <= i0 + 1) ? s0 + biasLUT[max(i0 - jj, 0)] : -1e30f;
                    s1 = (jj <= i1 + 1) ? s1 + biasLUT[max(i1 - jj, 0)] : -1e30f;
                } else {
                    if (jj >= Ltot) { s0 = -1e30f; s1 = -1e30f; }
                }
                cs[nt][e] = s0; cs[nt][2 + e] = s1;
                tm0 = fmaxf(tm0, s0); tm1 = fmaxf(tm1, s1);
            }
        }
        tm0 = fmaxf(tm0, __shfl_xor_sync(0xffffffffu, tm0, 1));
        tm0 = fmaxf(tm0, __shfl_xor_sync(0xffffffffu, tm0, 2));
        tm1 = fmaxf(tm1, __shfl_xor_sync(0xffffffffu, tm1, 1));
        tm1 = fmaxf(tm1, __shfl_xor_sync(0xffffffffu, tm1, 2));

        float mn0 = fmaxf(m0, tm0), mn1 = fmaxf(m1, tm1);
        float sc0 = __expf(m0 - mn0), sc1 = __expf(m1 - mn1);
        float ps0 = 0.f, ps1 = 0.f;
        #pragma unroll
        for (int nt = 0; nt < 8; nt++) {
            float p00 = __expf(cs[nt][0] - mn0);
            float p01 = __expf(cs[nt][1] - mn0);
            float p10 = __expf(cs[nt][2] - mn1);
            float p11 = __expf(cs[nt][3] - mn1);
            ps0 += p00 + p01; ps1 += p10 + p11;
            int c = nt * 8 + gk * 2;
            *(float2*)&Ps[r0    ][c] = make_float2(f2tf(p00), f2tf(p01));
            *(float2*)&Ps[r0 + 8][c] = make_float2(f2tf(p10), f2tf(p11));
            co[nt][0] *= sc0; co[nt][1] *= sc0;
            co[nt][2] *= sc1; co[nt][3] *= sc1;
        }
        ps0 += __shfl_xor_sync(0xffffffffu, ps0, 1);
        ps0 += __shfl_xor_sync(0xffffffffu, ps0, 2);
        ps1 += __shfl_xor_sync(0xffffffffu, ps1, 1);
        ps1 += __shfl_xor_sync(0xffffffffu, ps1, 2);
        l0 = l0 * sc0 + ps0; l1 = l1 * sc1 + ps1;
        m0 = mn0; m1 = mn1;
        __syncthreads();

        #pragma unroll
        for (int ks = 0; ks < 64; ks += 8) {
            unsigned a[4];
            a[0] = __float_as_uint(Ps[r0    ][ks + gk]);
            a[1] = __float_as_uint(Ps[r0 + 8][ks + gk]);
            a[2] = __float_as_uint(Ps[r0    ][ks + gk + 4]);
            a[3] = __float_as_uint(Ps[r0 + 8][ks + gk + 4]);
            #pragma unroll
            for (int nt = 0; nt < 8; nt++) {
                unsigned bb[2];
                bb[0] = __float_as_uint(Vs[ks + gk    ][nt * 8 + gr]);
                bb[1] = __float_as_uint(Vs[ks + gk + 4][nt * 8 + gr]);
                mma_tf32(co[nt], a, bb);
            }
        }
    }

    const float inv0 = 1.f / l0, inv1 = 1.f / l1;
    float* o0 = O + (long)(b * 1024 + q0 + r0) * 512 + h * 64;
    float* o1 = o0 + 8 * 512;
    #pragma unroll
    for (int nt = 0; nt < 8; nt++) {
        int c = nt * 8 + gk * 2;
        *(float2*)(o0 + c) = make_float2(f2tf(co[nt][0] * inv0), f2tf(co[nt][1] * inv0));
        *(float2*)(o1 + c) = make_float2(f2tf(co[nt][2] * inv1), f2tf(co[nt][3] * inv1));
    }
}

// ---------------- LayerNorm: 0=plain(tf32-rounded out), 2=stable(fp32 out) ----
template<int MODE>
__global__ __launch_bounds__(256) void ln_kernel(
    const float* __restrict__ in, const float* __restrict__ gam,
    float* __restrict__ out, int C)
{
    __shared__ float sred[8];
    long row = blockIdx.x;
    const float* x = in + row * (long)C;
    int tid = threadIdx.x;
    bool two = (C > 256);
    float v0 = x[tid];
    float v1 = two ? x[tid + 256] : 0.f;

    if (MODE == 2) {
        float mx = two ? fmaxf(v0, v1) : v0;
        mx = blockMax(mx, sred);
        float inv = 1.0f / mx;
        v0 *= inv; v1 *= inv;
    }
    float s = blockSum(v0 + v1, sred);
    float mu = s / (float)C;
    float d0 = v0 - mu, d1 = v1 - mu;
    float sq = d0 * d0 + (two ? d1 * d1 : 0.f);
    sq = blockSum(sq, sred);
    float rstd = rsqrtf(sq / (float)C + 1e-5f);

    float o0 = d0 * rstd * gam[tid];
    if (MODE == 0) o0 = f2tf(o0);
    out[row * (long)C + tid] = o0;
    if (two) {
        float o1 = d1 * rstd * gam[tid + 256];
        if (MODE == 0) o1 = f2tf(o1);
        out[row * (long)C + tid + 256] = o1;
    }
}

// ---- fused: X = X + LN(T)*g1 ; XN = tf32(LN(X)*g2)   (C = 512) ----
__global__ __launch_bounds__(256) void ln_res_ln(
    const float* __restrict__ T, const float* __restrict__ g1,
    const float* __restrict__ g2,
    float* __restrict__ X, float* __restrict__ XN)
{
    __shared__ float sred[8];
    long row = blockIdx.x;
    int tid = threadIdx.x;
    const float* t = T + row * 512;
    float v0 = t[tid], v1 = t[tid + 256];

    float s = blockSum(v0 + v1, sred);
    float mu = s * (1.0f / 512.0f);
    float d0 = v0 - mu, d1 = v1 - mu;
    float sq = blockSum(d0 * d0 + d1 * d1, sred);
    float rstd = rsqrtf(sq * (1.0f / 512.0f) + 1e-5f);

    float x0 = d0 * rstd * g1[tid]       + X[row * 512 + tid];
    float x1 = d1 * rstd * g1[tid + 256] + X[row * 512 + tid + 256];
    X[row * 512 + tid]       = x0;
    X[row * 512 + tid + 256] = x1;

    float s2 = blockSum(x0 + x1, sred);
    float mu2 = s2 * (1.0f / 512.0f);
    float e0 = x0 - mu2, e1 = x1 - mu2;
    float sq2 = blockSum(e0 * e0 + e1 * e1, sred);
    float rstd2 = rsqrtf(sq2 * (1.0f / 512.0f) + 1e-5f);

    XN[row * 512 + tid]       = f2tf(e0 * rstd2 * g2[tid]);
    XN[row * 512 + tid + 256] = f2tf(e1 * rstd2 * g2[tid + 256]);
}

// ---------------- KV prepare ----------------
template<bool ROT>
__global__ void prep_kv(const float* __restrict__ src, int ld, int koff,
                        const float* __restrict__ nullkv,
                        float* __restrict__ Kt, float* __restrict__ V, int srcN)
{
    int t = blockIdx.x;
    int b = blockIdx.y;
    int d = threadIdx.x;
    const float* kv = src + ((long)b * srcN + t) * ld + koff;
    float k = kv[d], v = kv[64 + d];
    V[((long)b * LDS_ + (t + 1)) * 64 + d] = v;
    float kr = k;
    if (ROT && d < 32) {
        int i = d & 15;
        float f = (float)t * powf(10000.0f, -(float)i * 0.0625f);
        float s, c; sincosf(f, &s, &c);
        float p = kv[(d < 16) ? d + 16 : d - 16];
        kr = (d < 16) ? (k * c - p * s) : (k * c + p * s);
    }
    Kt[((long)b * 64 + d) * LDS_ + (t + 1)] = kr;
    if (t == 0) {
        V[((long)b * LDS_) * 64 + d] = nullkv[64 + d];
        Kt[((long)b * 64 + d) * LDS_] = nullkv[d];
    }
    if (t < 15) {
        V[((long)b * LDS_ + srcN + 1 + t) * 64 + d] = 0.f;
    }
}

// ---------------- FFN gate (tf32-rounded out) ----------------
__global__ __launch_bounds__(256) void silu_gate(const float* __restrict__ H1,
                                                 float* __restrict__ G)
{
    long idx = (long)blockIdx.x * 256 + threadIdx.x;
    long r = idx >> 11, c = idx & 2047;
    float hh = H1[r * 4096 + c];
    float gt = H1[r * 4096 + 2048 + c];
    G[idx] = f2tf(hh * gt / (1.0f + expf(-gt)));
}

// ---------------- host helpers ----------------
static inline void gemm(const float* A, int lda,
                        const float* Bm, int ldb,
                        float* C, int ldc,
                        int M, int N, int K,
                        const float* Res = nullptr, int ldr = 0)
{
    dim3 g(N / 128, M / 128, 1);
    if (Res) tgemm_k<1><<<g, 256, TGEMM_SMEM>>>(A, lda, Bm, ldb, C, ldc, Res, ldr, N, K);
    else     tgemm_k<0><<<g, 256, TGEMM_SMEM>>>(A, lda, Bm, ldb, C, ldc, nullptr, 0, N, K);
}

static inline void round_w(const float* src, float* dst, long nfloats)
{
    round_tf32<<<(unsigned)(nfloats / 1024), 256>>>(src, dst);
}

#define FLASH_SMEM ((4 * 64 * 68 + 1024) * (int)sizeof(float))

extern "C" void kernel_launch(void* const* d_in, const int* in_sizes, int n_in,
                              void* d_out, int out_size)
{
    const float* x         = (const float*)d_in[0];
    const float* ctx       = (const float*)d_in[1];
    const float* rel_emb   = (const float*)d_in[2];
    const float* sa_norm_g = (const float*)d_in[3];
    const float* sa_wq     = (const float*)d_in[4];
    const float* sa_wkv    = (const float*)d_in[5];
    const float* sa_nkv    = (const float*)d_in[6];
    const float* sa_wo     = (const float*)d_in[7];
    const float* sa_out_g  = (const float*)d_in[8];
    const float* ca_norm_g = (const float*)d_in[9];
    const float* ca_ctx_g  = (const float*)d_in[10];
    const float* ca_wq     = (const float*)d_in[11];
    const float* ca_wkv    = (const float*)d_in[12];
    const float* ca_nkv    = (const float*)d_in[13];
    const float* ca_wo     = (const float*)d_in[14];
    const float* ca_out_g  = (const float*)d_in[15];
    const float* ff_norm_g = (const float*)d_in[16];
    const float* ff_w1     = (const float*)d_in[17];
    const float* ff_w2     = (const float*)d_in[18];
    const float* norm_g    = (const float*)d_in[19];

    float *pX, *pXN, *pQ, *pQKV, *pKVp, *pKt, *pV, *pO, *pT, *pH1, *pG, *pCTXN;
    float *pW, *pWsawo, *pWcawq, *pWcawo, *pWff1, *pWff2;
    cudaGetSymbolAddress((void**)&pX,    g_X);
    cudaGetSymbolAddress((void**)&pXN,   g_XN);
    cudaGetSymbolAddress((void**)&pQ,    g_Q);
    cudaGetSymbolAddress((void**)&pQKV,  g_QKV);
    cudaGetSymbolAddress((void**)&pKVp,  g_KVp);
    cudaGetSymbolAddress((void**)&pKt,   g_Kt);
    cudaGetSymbolAddress((void**)&pV,    g_V);
    cudaGetSymbolAddress((void**)&pO,    g_O);
    cudaGetSymbolAddress((void**)&pT,    g_T);
    cudaGetSymbolAddress((void**)&pH1,   g_H1);
    cudaGetSymbolAddress((void**)&pG,    g_G);
    cudaGetSymbolAddress((void**)&pCTXN, g_CTXN);
    cudaGetSymbolAddress((void**)&pW,     g_Wqkv);
    cudaGetSymbolAddress((void**)&pWsawo, g_Wsawo);
    cudaGetSymbolAddress((void**)&pWcawq, g_Wcawq);
    cudaGetSymbolAddress((void**)&pWcawo, g_Wcawo);
    cudaGetSymbolAddress((void**)&pWff1,  g_Wff1);
    cudaGetSymbolAddress((void**)&pWff2,  g_Wff2);

    cudaFuncSetAttribute(flash_attn<true>,
                         cudaFuncAttributeMaxDynamicSharedMemorySize, FLASH_SMEM);
    cudaFuncSetAttribute(flash_attn<false>,
                         cudaFuncAttributeMaxDynamicSharedMemorySize, FLASH_SMEM);
    cudaFuncSetAttribute(tgemm_k<0>,
                         cudaFuncAttributeMaxDynamicSharedMemorySize, TGEMM_SMEM);
    cudaFuncSetAttribute(tgemm_k<1>,
                         cudaFuncAttributeMaxDynamicSharedMemorySize, TGEMM_SMEM);

    cudaMemcpyAsync(pX, x, (size_t)Bsz * Nq * Dm * sizeof(float),
                    cudaMemcpyDeviceToDevice);
    pack_qkv<<<1920, 256>>>(sa_wq, sa_wkv, pW);
    round_w(sa_wo, pWsawo, (long)Ll * Dm * Dm);
    round_w(ca_wq, pWcawq, (long)Ll * Dm * Dm);
    round_w(ca_wo, pWcawo, (long)Ll * Dm * Dm);
    round_w(ff_w1, pWff1,  (long)Ll * Dm * 2 * FIi);
    round_w(ff_w2, pWff2,  (long)Ll * FIi * Dm);

    for (int l = 0; l < Ll; l++) {
        // ===== self attention =====
        ln_kernel<0><<<4096, 256>>>(pX, sa_norm_g + l * 512, pXN, 512);
        gemm(pXN, 512, pW + (long)l * 512 * 640, 640, pQKV, 640, 4096, 640, 512);
        prep_kv<true><<<dim3(1024, 4), 64>>>(pQKV, 640, 512,
                                             sa_nkv + l * 128, pKt, pV, 1024);
        flash_attn<true><<<dim3(16, 8, 4), 128, FLASH_SMEM>>>(
            pQKV, 640, pKt, pV, pO, rel_emb, 1025);
        gemm(pO, 512, pWsawo + (long)l * 512 * 512, 512, pT, 512, 4096, 512, 512);
        ln_res_ln<<<4096, 256>>>(pT, sa_out_g + l * 512, ca_norm_g + l * 512, pX, pXN);

        // ===== cross attention =====
        ln_kernel<0><<<2048, 256>>>(ctx, ca_ctx_g + l * 256, pCTXN, 256);
        gemm(pXN, 512, pWcawq + (long)l * 512 * 512, 512, pQ, 512, 4096, 512, 512);
        sgemm64_k<<<dim3(2, 32), 128>>>(pCTXN, 256,
                                        ca_wkv + (long)l * 256 * 128, 128,
                                        pKVp, 128, 256);
        prep_kv<false><<<dim3(512, 4), 64>>>(pKVp, 128, 0,
                                             ca_nkv + l * 128, pKt, pV, 512);
        flash_attn<false><<<dim3(16, 8, 4), 128, FLASH_SMEM>>>(
            pQ, 512, pKt, pV, pO, nullptr, 513);
        gemm(pO, 512, pWcawo + (long)l * 512 * 512, 512, pT, 512, 4096, 512, 512);
        ln_res_ln<<<4096, 256>>>(pT, ca_out_g + l * 512, ff_norm_g + l * 512, pX, pXN);

        // ===== feed forward =====
        gemm(pXN, 512, pWff1 + (long)l * 512 * 4096, 4096, pH1, 4096, 4096, 4096, 512);
        silu_gate<<<32768, 256>>>(pH1, pG);
        gemm(pG, 2048, pWff2 + (long)l * 2048 * 512, 512, pX, 512, 4096, 512, 2048, pX, 512);
    }

    ln_kernel<2><<<4096, 256>>>(pX, norm_g, (float*)d_out, 512);
}